// round 1
// baseline (speedup 1.0000x reference)
#include <cuda_runtime.h>
#include <cuda_bf16.h>
#include <cstdint>

// Problem constants
#define BATCH   4
#define SEQ     2048
#define DEMB    1024
#define NHEADS  16
#define HDIM    64
#define MROWS   (BATCH * SEQ)   // 8192

// ---------------- scratch (device globals: no runtime allocation allowed) ---
__device__ float g_Q[(size_t)MROWS * DEMB];
__device__ float g_K[(size_t)MROWS * DEMB];
__device__ float g_V[(size_t)MROWS * DEMB];
__device__ float g_A[(size_t)MROWS * DEMB];

// ---------------- GEMM: C[M,N] = A[M,K] @ W[K,N] + bias[N] (all row-major) --
#define BM 128
#define BN 128
#define BK 16
#define ASTRIDE 132   // BM + 4 pad

__global__ void __launch_bounds__(256) gemm_bias_kernel(
    const float* __restrict__ A, const float* __restrict__ W,
    const float* __restrict__ bias, float* __restrict__ C,
    int M, int N, int K)
{
    __shared__ float As[BK][ASTRIDE];
    __shared__ float Bs[BK][BN];

    const int tid = threadIdx.x;
    const int bx = blockIdx.x;       // N tile
    const int by = blockIdx.y;       // M tile
    const int tx = tid & 15;
    const int ty = tid >> 4;

    const float* Ab = A + (size_t)by * BM * K;
    const float* Wb = W + (size_t)bx * BN;

    float acc[8][8];
#pragma unroll
    for (int m = 0; m < 8; m++)
#pragma unroll
        for (int n = 0; n < 8; n++) acc[m][n] = 0.0f;

    for (int k0 = 0; k0 < K; k0 += BK) {
        // A tile: 128 rows x 16 k  (512 float4, 2 per thread), stored transposed
#pragma unroll
        for (int i = 0; i < 2; i++) {
            int f   = tid + i * 256;
            int row = f >> 2;              // 0..127
            int kq  = (f & 3) << 2;        // 0,4,8,12
            float4 v = *(const float4*)(Ab + (size_t)row * K + k0 + kq);
            As[kq + 0][row] = v.x;
            As[kq + 1][row] = v.y;
            As[kq + 2][row] = v.z;
            As[kq + 3][row] = v.w;
        }
        // B tile: 16 k x 128 n (512 float4, 2 per thread), natural layout
#pragma unroll
        for (int i = 0; i < 2; i++) {
            int f  = tid + i * 256;
            int kr = f >> 5;               // 0..15
            int nq = (f & 31) << 2;        // 0..124
            *(float4*)(&Bs[kr][nq]) = *(const float4*)(Wb + (size_t)(k0 + kr) * N + nq);
        }
        __syncthreads();

#pragma unroll
        for (int k = 0; k < BK; k++) {
            float ar[8], br[8];
#pragma unroll
            for (int m = 0; m < 8; m++) ar[m] = As[k][ty * 8 + m];
#pragma unroll
            for (int n = 0; n < 8; n++) br[n] = Bs[k][tx * 8 + n];
#pragma unroll
            for (int m = 0; m < 8; m++)
#pragma unroll
                for (int n = 0; n < 8; n++) acc[m][n] += ar[m] * br[n];
        }
        __syncthreads();
    }

    // epilogue: add bias, vectorized store
#pragma unroll
    for (int m = 0; m < 8; m++) {
        int row = by * BM + ty * 8 + m;
#pragma unroll
        for (int n = 0; n < 8; n += 4) {
            int col = bx * BN + tx * 8 + n;
            float4 b4 = *(const float4*)(bias + col);
            float4 o;
            o.x = acc[m][n + 0] + b4.x;
            o.y = acc[m][n + 1] + b4.y;
            o.z = acc[m][n + 2] + b4.z;
            o.w = acc[m][n + 3] + b4.w;
            *(float4*)(C + (size_t)row * N + col) = o;
        }
    }
}

// ---------------- attention: flash-style, fp32, online softmax --------------
// grid: (SEQ/BQ, NHEADS, BATCH), 256 threads.
// thread (qg = tid>>4, cg = tid&15) owns 8 q-rows (qg*8..+7) and
// 4 kv-cols / 4 d-cols (cg*4..+3).
#define BQ  128
#define BKV 64
#define PST 68   // padded row stride (floats), multiple of 4 for float4

__global__ void __launch_bounds__(256, 2) attn_kernel(
    const float* __restrict__ Q, const float* __restrict__ K,
    const float* __restrict__ V, float* __restrict__ O)
{
    extern __shared__ float sm[];
    float* Qs = sm;                       // [BQ ][PST]  Qs[qrow][d]
    float* Kt = Qs + BQ * PST;            // [HDIM][PST] Kt[d][kvcol] (transposed)
    float* Vs = Kt + HDIM * PST;          // [BKV][PST]  Vs[kvrow][d]
    float* Ps = Vs + BKV * PST;           // [BQ ][PST]  Ps[qrow][kvcol]

    const int tid = threadIdx.x;
    const int qg  = tid >> 4;             // 0..15
    const int cg  = tid & 15;             // 0..15
    const int qblk = blockIdx.x;
    const int h    = blockIdx.y;
    const int b    = blockIdx.z;

    const float* Qg = Q + ((size_t)(b * SEQ + qblk * BQ)) * DEMB + h * HDIM;
    const float* Kg = K + ((size_t)(b * SEQ)) * DEMB + h * HDIM;
    const float* Vg = V + ((size_t)(b * SEQ)) * DEMB + h * HDIM;

    // load Q tile: 128 x 64 floats = 2048 float4, 8 per thread
#pragma unroll
    for (int i = 0; i < 8; i++) {
        int f = tid + i * 256;
        int r = f >> 4;                 // 0..127
        int c = (f & 15) << 2;          // 0..60
        float4 v = *(const float4*)(Qg + (size_t)r * DEMB + c);
        *(float4*)(Qs + r * PST + c) = v;
    }

    float m_r[8], l_r[8], acc[8][4];
#pragma unroll
    for (int r = 0; r < 8; r++) {
        m_r[r] = -1e30f; l_r[r] = 0.0f;
#pragma unroll
        for (int c = 0; c < 4; c++) acc[r][c] = 0.0f;
    }
    __syncthreads();

    for (int kb = 0; kb < SEQ; kb += BKV) {
        // load K (transposed into Kt[d][kvrow]) and V (natural)
#pragma unroll
        for (int i = 0; i < 4; i++) {
            int f = tid + i * 256;
            int r = f >> 4;             // kv row 0..63
            int c = (f & 15) << 2;      // d
            float4 k4 = *(const float4*)(Kg + (size_t)(kb + r) * DEMB + c);
            Kt[(c + 0) * PST + r] = k4.x;
            Kt[(c + 1) * PST + r] = k4.y;
            Kt[(c + 2) * PST + r] = k4.z;
            Kt[(c + 3) * PST + r] = k4.w;
            float4 v4 = *(const float4*)(Vg + (size_t)(kb + r) * DEMB + c);
            *(float4*)(Vs + r * PST + c) = v4;
        }
        __syncthreads();

        // scores: s[r][c] = sum_d Q[qrow][d] * K[kvcol][d]
        float s[8][4];
#pragma unroll
        for (int r = 0; r < 8; r++)
#pragma unroll
            for (int c = 0; c < 4; c++) s[r][c] = 0.0f;

#pragma unroll 4
        for (int d = 0; d < HDIM; d += 4) {
            float4 kx[4];
#pragma unroll
            for (int dd = 0; dd < 4; dd++)
                kx[dd] = *(const float4*)(Kt + (d + dd) * PST + cg * 4);
#pragma unroll
            for (int r = 0; r < 8; r++) {
                float4 q4 = *(const float4*)(Qs + (qg * 8 + r) * PST + d);
                s[r][0] += q4.x * kx[0].x + q4.y * kx[1].x + q4.z * kx[2].x + q4.w * kx[3].x;
                s[r][1] += q4.x * kx[0].y + q4.y * kx[1].y + q4.z * kx[2].y + q4.w * kx[3].y;
                s[r][2] += q4.x * kx[0].z + q4.y * kx[1].z + q4.z * kx[2].z + q4.w * kx[3].z;
                s[r][3] += q4.x * kx[0].w + q4.y * kx[1].w + q4.z * kx[2].w + q4.w * kx[3].w;
            }
        }

        // online softmax update (row stats reduced across 16 lanes sharing qg)
#pragma unroll
        for (int r = 0; r < 8; r++) {
#pragma unroll
            for (int c = 0; c < 4; c++) s[r][c] *= 0.125f;   // 1/sqrt(64)
            float mx = fmaxf(fmaxf(s[r][0], s[r][1]), fmaxf(s[r][2], s[r][3]));
            mx = fmaxf(mx, __shfl_xor_sync(0xffffffffu, mx, 1));
            mx = fmaxf(mx, __shfl_xor_sync(0xffffffffu, mx, 2));
            mx = fmaxf(mx, __shfl_xor_sync(0xffffffffu, mx, 4));
            mx = fmaxf(mx, __shfl_xor_sync(0xffffffffu, mx, 8));
            float mnew = fmaxf(m_r[r], mx);
            float corr = __expf(m_r[r] - mnew);
            float ps = 0.0f;
#pragma unroll
            for (int c = 0; c < 4; c++) { s[r][c] = __expf(s[r][c] - mnew); ps += s[r][c]; }
            ps += __shfl_xor_sync(0xffffffffu, ps, 1);
            ps += __shfl_xor_sync(0xffffffffu, ps, 2);
            ps += __shfl_xor_sync(0xffffffffu, ps, 4);
            ps += __shfl_xor_sync(0xffffffffu, ps, 8);
            l_r[r] = l_r[r] * corr + ps;
            m_r[r] = mnew;
#pragma unroll
            for (int c = 0; c < 4; c++) acc[r][c] *= corr;
            *(float4*)(Ps + (qg * 8 + r) * PST + cg * 4) =
                make_float4(s[r][0], s[r][1], s[r][2], s[r][3]);
        }
        __syncthreads();

        // PV: acc[r][c] += sum_j P[qrow][j] * V[j][cg*4+c]
#pragma unroll 4
        for (int j = 0; j < BKV; j += 4) {
            float4 v4[4];
#pragma unroll
            for (int jj = 0; jj < 4; jj++)
                v4[jj] = *(const float4*)(Vs + (j + jj) * PST + cg * 4);
#pragma unroll
            for (int r = 0; r < 8; r++) {
                float4 p4 = *(const float4*)(Ps + (qg * 8 + r) * PST + j);
                acc[r][0] += p4.x * v4[0].x + p4.y * v4[1].x + p4.z * v4[2].x + p4.w * v4[3].x;
                acc[r][1] += p4.x * v4[0].y + p4.y * v4[1].y + p4.z * v4[2].y + p4.w * v4[3].y;
                acc[r][2] += p4.x * v4[0].z + p4.y * v4[1].z + p4.z * v4[2].z + p4.w * v4[3].z;
                acc[r][3] += p4.x * v4[0].w + p4.y * v4[1].w + p4.z * v4[2].w + p4.w * v4[3].w;
            }
        }
        __syncthreads();
    }

    // write: O[(b*SEQ + s)][h*64 + d]  (this IS the [B,S,H*D] re-merge)
#pragma unroll
    for (int r = 0; r < 8; r++) {
        float inv = 1.0f / l_r[r];
        float4 o = make_float4(acc[r][0] * inv, acc[r][1] * inv,
                               acc[r][2] * inv, acc[r][3] * inv);
        *(float4*)(O + ((size_t)(b * SEQ + qblk * BQ + qg * 8 + r)) * DEMB
                     + h * HDIM + cg * 4) = o;
    }
}

// ---------------- launch -----------------------------------------------------
extern "C" void kernel_launch(void* const* d_in, const int* in_sizes, int n_in,
                              void* d_out, int out_size)
{
    const float* x  = (const float*)d_in[0];
    const float* qw = (const float*)d_in[1];
    const float* qb = (const float*)d_in[2];
    const float* kw = (const float*)d_in[3];
    const float* kb = (const float*)d_in[4];
    const float* vw = (const float*)d_in[5];
    const float* vb = (const float*)d_in[6];
    const float* ow = (const float*)d_in[7];
    const float* ob = (const float*)d_in[8];
    float* out = (float*)d_out;

    float *Q, *K, *V, *A;
    cudaGetSymbolAddress((void**)&Q, g_Q);
    cudaGetSymbolAddress((void**)&K, g_K);
    cudaGetSymbolAddress((void**)&V, g_V);
    cudaGetSymbolAddress((void**)&A, g_A);

    const int attn_smem = (BQ + HDIM + BKV + BQ) * PST * sizeof(float); // 104448
    cudaFuncSetAttribute(attn_kernel, cudaFuncAttributeMaxDynamicSharedMemorySize,
                         attn_smem);

    dim3 gemm_grid(DEMB / BN, MROWS / BM);   // (8, 64)
    gemm_bias_kernel<<<gemm_grid, 256>>>(x, qw, qb, Q, MROWS, DEMB, DEMB);
    gemm_bias_kernel<<<gemm_grid, 256>>>(x, kw, kb, K, MROWS, DEMB, DEMB);
    gemm_bias_kernel<<<gemm_grid, 256>>>(x, vw, vb, V, MROWS, DEMB, DEMB);

    dim3 attn_grid(SEQ / BQ, NHEADS, BATCH); // (16, 16, 4)
    attn_kernel<<<attn_grid, 256, attn_smem>>>(Q, K, V, A);

    gemm_bias_kernel<<<gemm_grid, 256>>>(A, ow, ob, out, MROWS, DEMB, DEMB);
}

// round 3
// speedup vs baseline: 1.3618x; 1.3618x over previous
#include <cuda_runtime.h>
#include <cuda_bf16.h>
#include <cstdint>

// Problem constants
#define BATCH   4
#define SEQ     2048
#define DEMB    1024
#define NHEADS  16
#define HDIM    64
#define MROWS   (BATCH * SEQ)   // 8192

// ---------------- scratch (device globals: no runtime allocation allowed) ---
__device__ float g_Q[(size_t)MROWS * DEMB];
__device__ float g_K[(size_t)MROWS * DEMB];
__device__ float g_V[(size_t)MROWS * DEMB];
__device__ float g_A[(size_t)MROWS * DEMB];
__device__ __nv_bfloat16 g_xhi[(size_t)MROWS * DEMB];
__device__ __nv_bfloat16 g_xlo[(size_t)MROWS * DEMB];
__device__ __nv_bfloat16 g_wthi[(size_t)4 * DEMB * DEMB];
__device__ __nv_bfloat16 g_wtlo[(size_t)4 * DEMB * DEMB];

// ---------------- helpers (family-agnostic ISA only: sm_80-era) -------------
__device__ __forceinline__ uint32_t s2u(const void* p) {
    uint32_t a;
    asm("{ .reg .u64 t; cvta.to.shared.u64 t, %1; cvt.u32.u64 %0, t; }"
        : "=r"(a) : "l"(p));
    return a;
}

__device__ __forceinline__ void cp16(uint32_t dst, const void* src) {
    asm volatile("cp.async.cg.shared.global [%0], [%1], 16;"
                 :: "r"(dst), "l"(src));
}
__device__ __forceinline__ void cp_commit() {
    asm volatile("cp.async.commit_group;");
}
template <int N>
__device__ __forceinline__ void cp_wait() {
    asm volatile("cp.async.wait_group %0;" :: "n"(N));
}

__device__ __forceinline__ void ldsm_x4(uint32_t* r, uint32_t addr) {
    asm volatile("ldmatrix.sync.aligned.m8n8.x4.shared.b16 {%0,%1,%2,%3}, [%4];"
                 : "=r"(r[0]), "=r"(r[1]), "=r"(r[2]), "=r"(r[3]) : "r"(addr));
}

__device__ __forceinline__ void mma16816(float* c, const uint32_t* a,
                                         const uint32_t* b) {
    asm volatile(
        "mma.sync.aligned.m16n8k16.row.col.f32.bf16.bf16.f32 "
        "{%0,%1,%2,%3}, {%4,%5,%6,%7}, {%8,%9}, {%0,%1,%2,%3};"
        : "+f"(c[0]), "+f"(c[1]), "+f"(c[2]), "+f"(c[3])
        : "r"(a[0]), "r"(a[1]), "r"(a[2]), "r"(a[3]), "r"(b[0]), "r"(b[1]));
}

// ---------------- fp32 -> bf16 hi/lo split (elementwise) --------------------
__global__ void __launch_bounds__(256) convert_split_kernel(
    const float* __restrict__ in, __nv_bfloat16* __restrict__ hi,
    __nv_bfloat16* __restrict__ lo)
{
    size_t i = (size_t)blockIdx.x * blockDim.x + threadIdx.x;  // over n/4
    float4 v = ((const float4*)in)[i];
    float vv[4] = {v.x, v.y, v.z, v.w};
    ushort4 h, l;
    unsigned short* hp = &h.x;
    unsigned short* lp = &l.x;
#pragma unroll
    for (int j = 0; j < 4; j++) {
        __nv_bfloat16 hb = __float2bfloat16_rn(vv[j]);
        float res = vv[j] - __bfloat162float(hb);
        __nv_bfloat16 lb = __float2bfloat16_rn(res);
        hp[j] = __bfloat16_as_ushort(hb);
        lp[j] = __bfloat16_as_ushort(lb);
    }
    ((ushort4*)hi)[i] = h;
    ((ushort4*)lo)[i] = l;
}

// ---------------- W[K,N] fp32 -> W^T[N,K] bf16 hi/lo (transpose + split) ----
__global__ void __launch_bounds__(256) wconvert_kernel(
    const float* __restrict__ W, __nv_bfloat16* __restrict__ Thi,
    __nv_bfloat16* __restrict__ Tlo)
{
    __shared__ float t[32][33];
    int n0 = blockIdx.x * 32;
    int k0 = blockIdx.y * 32;
    int x = threadIdx.x;   // 0..31
    int y = threadIdx.y;   // 0..7
#pragma unroll
    for (int r = y; r < 32; r += 8)
        t[r][x] = W[(size_t)(k0 + r) * DEMB + n0 + x];
    __syncthreads();
#pragma unroll
    for (int r = y; r < 32; r += 8) {
        float v = t[x][r];                 // = W[k0+x][n0+r]
        __nv_bfloat16 hb = __float2bfloat16_rn(v);
        float res = v - __bfloat162float(hb);
        __nv_bfloat16 lb = __float2bfloat16_rn(res);
        size_t o = (size_t)(n0 + r) * DEMB + k0 + x;
        Thi[o] = hb;
        Tlo[o] = lb;
    }
}

// ---------------- HMMA GEMM: C[M,N] = A @ B^T + bias ------------------------
// A: bf16 hi/lo [M,K] row-major. B: bf16 hi/lo [N,K] row-major (pre-transposed).
// 3 mma passes: hi*hi + hi*lo + lo*hi; fp32 accumulators.
#define GBK  32
#define ASTR 40                          // smem row stride in bf16 (32 + 8 pad)
#define TILEB (128 * ASTR * 2)           // one array tile = 10240 B
#define STAGEB (4 * TILEB)               // {Ah, Al, Bh, Bl}
#define GSMEM (2 * STAGEB)               // double buffered = 81920 B

__global__ void __launch_bounds__(256, 1) gemm_mma_kernel(
    const __nv_bfloat16* __restrict__ Ahi, const __nv_bfloat16* __restrict__ Alo,
    const __nv_bfloat16* __restrict__ Bhi, const __nv_bfloat16* __restrict__ Blo,
    const float* __restrict__ bias, float* __restrict__ C)
{
    extern __shared__ __align__(128) char smg[];
    const int tid  = threadIdx.x;
    const int wid  = tid >> 5;
    const int lane = tid & 31;
    const int bn = blockIdx.x;
    const int bm = blockIdx.y;
    const int wm = wid >> 2;             // 0..1
    const int wn = wid & 3;              // 0..3
    const uint32_t sbase = s2u(smg);

    const __nv_bfloat16* srcs[4] = {
        Ahi + (size_t)bm * 128 * DEMB, Alo + (size_t)bm * 128 * DEMB,
        Bhi + (size_t)bn * 128 * DEMB, Blo + (size_t)bn * 128 * DEMB };

    // per-thread load slots: 512 16B-chunks per array, 2 per thread
    const int c0 = tid * 2;
    const int lr0 = c0 >> 2, lc0 = c0 & 3;
    const int lr1 = (c0 + 1) >> 2, lc1 = (c0 + 1) & 3;

    auto load_tile = [&](int stage, int k0) {
        uint32_t st = sbase + stage * STAGEB;
#pragma unroll
        for (int t = 0; t < 4; t++) {
            const __nv_bfloat16* src = srcs[t] + k0;
            uint32_t dst = st + t * TILEB;
            cp16(dst + (lr0 * ASTR + lc0 * 8) * 2, src + (size_t)lr0 * DEMB + lc0 * 8);
            cp16(dst + (lr1 * ASTR + lc1 * 8) * 2, src + (size_t)lr1 * DEMB + lc1 * 8);
        }
    };

    float acc[4][4][4];
#pragma unroll
    for (int mt = 0; mt < 4; mt++)
#pragma unroll
        for (int nt = 0; nt < 4; nt++)
#pragma unroll
            for (int e = 0; e < 4; e++) acc[mt][nt][e] = 0.0f;

    // ldmatrix lane->address components
    const int lr = lane & 7, sec = lane >> 3;
    const int a_row = (sec & 1) * 8 + lr;       // row within 16x16 A tile
    const int a_kof = (sec >> 1) * 8;
    const int b_row = (sec >> 1) * 8 + lr;      // n within 16-row B pair
    const int b_kof = (sec & 1) * 8;

    load_tile(0, 0);
    cp_commit();

    const int NIT = DEMB / GBK;   // 32
    for (int i = 0; i < NIT; i++) {
        if (i + 1 < NIT) {
            load_tile((i + 1) & 1, (i + 1) * GBK);
            cp_commit();
            cp_wait<1>();
        } else {
            cp_wait<0>();
        }
        __syncthreads();

        uint32_t st = sbase + (i & 1) * STAGEB;
        uint32_t sAh = st, sAl = st + TILEB, sBh = st + 2 * TILEB, sBl = st + 3 * TILEB;

#pragma unroll
        for (int ks = 0; ks < 2; ks++) {
            uint32_t ah[4][4], al[4][4];
#pragma unroll
            for (int mt = 0; mt < 4; mt++) {
                uint32_t off = ((wm * 64 + mt * 16 + a_row) * ASTR + ks * 16 + a_kof) * 2;
                ldsm_x4(ah[mt], sAh + off);
                ldsm_x4(al[mt], sAl + off);
            }
            uint32_t bh[4][2], bl[4][2];
#pragma unroll
            for (int p = 0; p < 2; p++) {     // each x4 covers 2 n-tiles
                uint32_t off = ((wn * 32 + p * 16 + b_row) * ASTR + ks * 16 + b_kof) * 2;
                uint32_t r4[4];
                ldsm_x4(r4, sBh + off);
                bh[p * 2][0] = r4[0]; bh[p * 2][1] = r4[1];
                bh[p * 2 + 1][0] = r4[2]; bh[p * 2 + 1][1] = r4[3];
                ldsm_x4(r4, sBl + off);
                bl[p * 2][0] = r4[0]; bl[p * 2][1] = r4[1];
                bl[p * 2 + 1][0] = r4[2]; bl[p * 2 + 1][1] = r4[3];
            }
#pragma unroll
            for (int mt = 0; mt < 4; mt++)
#pragma unroll
                for (int nt = 0; nt < 4; nt++) {
                    mma16816(acc[mt][nt], ah[mt], bh[nt]);
                    mma16816(acc[mt][nt], ah[mt], bl[nt]);
                    mma16816(acc[mt][nt], al[mt], bh[nt]);
                }
        }
        __syncthreads();
    }

    // epilogue: c-frag lane mapping: rows g, g+8; cols (lane&3)*2, +1
    const int g = lane >> 2;
    const int cc = (lane & 3) * 2;
#pragma unroll
    for (int mt = 0; mt < 4; mt++) {
        int row0 = bm * 128 + wm * 64 + mt * 16 + g;
#pragma unroll
        for (int nt = 0; nt < 4; nt++) {
            int col = bn * 128 + wn * 32 + nt * 8 + cc;
            float2 b2 = *(const float2*)(bias + col);
            float2 o0 = make_float2(acc[mt][nt][0] + b2.x, acc[mt][nt][1] + b2.y);
            float2 o1 = make_float2(acc[mt][nt][2] + b2.x, acc[mt][nt][3] + b2.y);
            *(float2*)(C + (size_t)row0 * DEMB + col) = o0;
            *(float2*)(C + (size_t)(row0 + 8) * DEMB + col) = o1;
        }
    }
}

// ---------------- attention: flash-style, fp32, online softmax (unchanged) --
#define BQ  128
#define BKV 64
#define PST 68   // padded row stride (floats)

__global__ void __launch_bounds__(256, 2) attn_kernel(
    const float* __restrict__ Q, const float* __restrict__ K,
    const float* __restrict__ V, float* __restrict__ O)
{
    extern __shared__ float sm[];
    float* Qs = sm;
    float* Kt = Qs + BQ * PST;
    float* Vs = Kt + HDIM * PST;
    float* Ps = Vs + BKV * PST;

    const int tid = threadIdx.x;
    const int qg  = tid >> 4;
    const int cg  = tid & 15;
    const int qblk = blockIdx.x;
    const int h    = blockIdx.y;
    const int b    = blockIdx.z;

    const float* Qg = Q + ((size_t)(b * SEQ + qblk * BQ)) * DEMB + h * HDIM;
    const float* Kg = K + ((size_t)(b * SEQ)) * DEMB + h * HDIM;
    const float* Vg = V + ((size_t)(b * SEQ)) * DEMB + h * HDIM;

#pragma unroll
    for (int i = 0; i < 8; i++) {
        int f = tid + i * 256;
        int r = f >> 4;
        int c = (f & 15) << 2;
        float4 v = *(const float4*)(Qg + (size_t)r * DEMB + c);
        *(float4*)(Qs + r * PST + c) = v;
    }

    float m_r[8], l_r[8], acc[8][4];
#pragma unroll
    for (int r = 0; r < 8; r++) {
        m_r[r] = -1e30f; l_r[r] = 0.0f;
#pragma unroll
        for (int c = 0; c < 4; c++) acc[r][c] = 0.0f;
    }
    __syncthreads();

    for (int kb = 0; kb < SEQ; kb += BKV) {
#pragma unroll
        for (int i = 0; i < 4; i++) {
            int f = tid + i * 256;
            int r = f >> 4;
            int c = (f & 15) << 2;
            float4 k4 = *(const float4*)(Kg + (size_t)(kb + r) * DEMB + c);
            Kt[(c + 0) * PST + r] = k4.x;
            Kt[(c + 1) * PST + r] = k4.y;
            Kt[(c + 2) * PST + r] = k4.z;
            Kt[(c + 3) * PST + r] = k4.w;
            float4 v4 = *(const float4*)(Vg + (size_t)(kb + r) * DEMB + c);
            *(float4*)(Vs + r * PST + c) = v4;
        }
        __syncthreads();

        float s[8][4];
#pragma unroll
        for (int r = 0; r < 8; r++)
#pragma unroll
            for (int c = 0; c < 4; c++) s[r][c] = 0.0f;

#pragma unroll 4
        for (int d = 0; d < HDIM; d += 4) {
            float4 kx[4];
#pragma unroll
            for (int dd = 0; dd < 4; dd++)
                kx[dd] = *(const float4*)(Kt + (d + dd) * PST + cg * 4);
#pragma unroll
            for (int r = 0; r < 8; r++) {
                float4 q4 = *(const float4*)(Qs + (qg * 8 + r) * PST + d);
                s[r][0] += q4.x * kx[0].x + q4.y * kx[1].x + q4.z * kx[2].x + q4.w * kx[3].x;
                s[r][1] += q4.x * kx[0].y + q4.y * kx[1].y + q4.z * kx[2].y + q4.w * kx[3].y;
                s[r][2] += q4.x * kx[0].z + q4.y * kx[1].z + q4.z * kx[2].z + q4.w * kx[3].z;
                s[r][3] += q4.x * kx[0].w + q4.y * kx[1].w + q4.z * kx[2].w + q4.w * kx[3].w;
            }
        }

#pragma unroll
        for (int r = 0; r < 8; r++) {
#pragma unroll
            for (int c = 0; c < 4; c++) s[r][c] *= 0.125f;
            float mx = fmaxf(fmaxf(s[r][0], s[r][1]), fmaxf(s[r][2], s[r][3]));
            mx = fmaxf(mx, __shfl_xor_sync(0xffffffffu, mx, 1));
            mx = fmaxf(mx, __shfl_xor_sync(0xffffffffu, mx, 2));
            mx = fmaxf(mx, __shfl_xor_sync(0xffffffffu, mx, 4));
            mx = fmaxf(mx, __shfl_xor_sync(0xffffffffu, mx, 8));
            float mnew = fmaxf(m_r[r], mx);
            float corr = __expf(m_r[r] - mnew);
            float ps = 0.0f;
#pragma unroll
            for (int c = 0; c < 4; c++) { s[r][c] = __expf(s[r][c] - mnew); ps += s[r][c]; }
            ps += __shfl_xor_sync(0xffffffffu, ps, 1);
            ps += __shfl_xor_sync(0xffffffffu, ps, 2);
            ps += __shfl_xor_sync(0xffffffffu, ps, 4);
            ps += __shfl_xor_sync(0xffffffffu, ps, 8);
            l_r[r] = l_r[r] * corr + ps;
            m_r[r] = mnew;
#pragma unroll
            for (int c = 0; c < 4; c++) acc[r][c] *= corr;
            *(float4*)(Ps + (qg * 8 + r) * PST + cg * 4) =
                make_float4(s[r][0], s[r][1], s[r][2], s[r][3]);
        }
        __syncthreads();

#pragma unroll 4
        for (int j = 0; j < BKV; j += 4) {
            float4 v4[4];
#pragma unroll
            for (int jj = 0; jj < 4; jj++)
                v4[jj] = *(const float4*)(Vs + (j + jj) * PST + cg * 4);
#pragma unroll
            for (int r = 0; r < 8; r++) {
                float4 p4 = *(const float4*)(Ps + (qg * 8 + r) * PST + j);
                acc[r][0] += p4.x * v4[0].x + p4.y * v4[1].x + p4.z * v4[2].x + p4.w * v4[3].x;
                acc[r][1] += p4.x * v4[0].y + p4.y * v4[1].y + p4.z * v4[2].y + p4.w * v4[3].y;
                acc[r][2] += p4.x * v4[0].z + p4.y * v4[1].z + p4.z * v4[2].z + p4.w * v4[3].z;
                acc[r][3] += p4.x * v4[0].w + p4.y * v4[1].w + p4.z * v4[2].w + p4.w * v4[3].w;
            }
        }
        __syncthreads();
    }

#pragma unroll
    for (int r = 0; r < 8; r++) {
        float inv = 1.0f / l_r[r];
        float4 o = make_float4(acc[r][0] * inv, acc[r][1] * inv,
                               acc[r][2] * inv, acc[r][3] * inv);
        *(float4*)(O + ((size_t)(b * SEQ + qblk * BQ + qg * 8 + r)) * DEMB
                     + h * HDIM + cg * 4) = o;
    }
}

// ---------------- launch -----------------------------------------------------
extern "C" void kernel_launch(void* const* d_in, const int* in_sizes, int n_in,
                              void* d_out, int out_size)
{
    const float* x  = (const float*)d_in[0];
    const float* qw = (const float*)d_in[1];
    const float* qb = (const float*)d_in[2];
    const float* kw = (const float*)d_in[3];
    const float* kb = (const float*)d_in[4];
    const float* vw = (const float*)d_in[5];
    const float* vb = (const float*)d_in[6];
    const float* ow = (const float*)d_in[7];
    const float* ob = (const float*)d_in[8];
    float* out = (float*)d_out;

    float *Q, *K, *V, *A;
    __nv_bfloat16 *xhi, *xlo, *wthi, *wtlo;
    cudaGetSymbolAddress((void**)&Q, g_Q);
    cudaGetSymbolAddress((void**)&K, g_K);
    cudaGetSymbolAddress((void**)&V, g_V);
    cudaGetSymbolAddress((void**)&A, g_A);
    cudaGetSymbolAddress((void**)&xhi, g_xhi);
    cudaGetSymbolAddress((void**)&xlo, g_xlo);
    cudaGetSymbolAddress((void**)&wthi, g_wthi);
    cudaGetSymbolAddress((void**)&wtlo, g_wtlo);

    const int attn_smem = (BQ + HDIM + BKV + BQ) * PST * sizeof(float);
    cudaFuncSetAttribute(attn_kernel, cudaFuncAttributeMaxDynamicSharedMemorySize,
                         attn_smem);
    cudaFuncSetAttribute(gemm_mma_kernel, cudaFuncAttributeMaxDynamicSharedMemorySize,
                         GSMEM);

    const size_t WSZ = (size_t)DEMB * DEMB;
    dim3 wgrid(32, 32), wblk(32, 8);
    dim3 ggrid(DEMB / 128, MROWS / 128);   // (8, 64)

    // split x into bf16 hi/lo
    convert_split_kernel<<<MROWS * DEMB / 4 / 256, 256>>>(x, xhi, xlo);
    // transpose + split weights: W[K,N] -> W^T[N,K] hi/lo
    wconvert_kernel<<<wgrid, wblk>>>(qw, wthi + 0 * WSZ, wtlo + 0 * WSZ);
    wconvert_kernel<<<wgrid, wblk>>>(kw, wthi + 1 * WSZ, wtlo + 1 * WSZ);
    wconvert_kernel<<<wgrid, wblk>>>(vw, wthi + 2 * WSZ, wtlo + 2 * WSZ);
    wconvert_kernel<<<wgrid, wblk>>>(ow, wthi + 3 * WSZ, wtlo + 3 * WSZ);

    // projections on HMMA tensor cores
    gemm_mma_kernel<<<ggrid, 256, GSMEM>>>(xhi, xlo, wthi + 0 * WSZ, wtlo + 0 * WSZ, qb, Q);
    gemm_mma_kernel<<<ggrid, 256, GSMEM>>>(xhi, xlo, wthi + 1 * WSZ, wtlo + 1 * WSZ, kb, K);
    gemm_mma_kernel<<<ggrid, 256, GSMEM>>>(xhi, xlo, wthi + 2 * WSZ, wtlo + 2 * WSZ, vb, V);

    dim3 attn_grid(SEQ / BQ, NHEADS, BATCH);
    attn_kernel<<<attn_grid, 256, attn_smem>>>(Q, K, V, A);

    // output projection
    convert_split_kernel<<<MROWS * DEMB / 4 / 256, 256>>>(A, xhi, xlo);
    gemm_mma_kernel<<<ggrid, 256, GSMEM>>>(xhi, xlo, wthi + 3 * WSZ, wtlo + 3 * WSZ, ob, out);
}

// round 4
// speedup vs baseline: 2.5931x; 1.9042x over previous
#include <cuda_runtime.h>
#include <cuda_bf16.h>
#include <cstdint>

// Problem constants
#define BATCH   4
#define SEQ     2048
#define DEMB    1024
#define NHEADS  16
#define HDIM    64
#define MROWS   (BATCH * SEQ)   // 8192

// ---------------- scratch (device globals) -----------------------------------
__device__ __nv_bfloat16 g_xhi[(size_t)MROWS * DEMB];
__device__ __nv_bfloat16 g_xlo[(size_t)MROWS * DEMB];
__device__ __nv_bfloat16 g_qh[(size_t)MROWS * DEMB];
__device__ __nv_bfloat16 g_ql[(size_t)MROWS * DEMB];
__device__ __nv_bfloat16 g_kh[(size_t)MROWS * DEMB];
__device__ __nv_bfloat16 g_kl[(size_t)MROWS * DEMB];
__device__ __nv_bfloat16 g_vh[(size_t)MROWS * DEMB];
__device__ __nv_bfloat16 g_vl[(size_t)MROWS * DEMB];
__device__ __nv_bfloat16 g_wthi[(size_t)4 * DEMB * DEMB];
__device__ __nv_bfloat16 g_wtlo[(size_t)4 * DEMB * DEMB];

// ---------------- helpers (family-agnostic ISA: sm_80/75-era) ----------------
__device__ __forceinline__ uint32_t s2u(const void* p) {
    uint32_t a;
    asm("{ .reg .u64 t; cvta.to.shared.u64 t, %1; cvt.u32.u64 %0, t; }"
        : "=r"(a) : "l"(p));
    return a;
}
__device__ __forceinline__ void cp16(uint32_t dst, const void* src) {
    asm volatile("cp.async.cg.shared.global [%0], [%1], 16;"
                 :: "r"(dst), "l"(src));
}
__device__ __forceinline__ void cp_commit() {
    asm volatile("cp.async.commit_group;");
}
template <int N>
__device__ __forceinline__ void cp_wait() {
    asm volatile("cp.async.wait_group %0;" :: "n"(N));
}
__device__ __forceinline__ void ldsm_x4(uint32_t* r, uint32_t addr) {
    asm volatile("ldmatrix.sync.aligned.m8n8.x4.shared.b16 {%0,%1,%2,%3}, [%4];"
                 : "=r"(r[0]), "=r"(r[1]), "=r"(r[2]), "=r"(r[3]) : "r"(addr));
}
__device__ __forceinline__ void ldsm_x4t(uint32_t* r, uint32_t addr) {
    asm volatile("ldmatrix.sync.aligned.m8n8.x4.trans.shared.b16 {%0,%1,%2,%3}, [%4];"
                 : "=r"(r[0]), "=r"(r[1]), "=r"(r[2]), "=r"(r[3]) : "r"(addr));
}
__device__ __forceinline__ void mma16816(float* c, const uint32_t* a,
                                         const uint32_t* b) {
    asm volatile(
        "mma.sync.aligned.m16n8k16.row.col.f32.bf16.bf16.f32 "
        "{%0,%1,%2,%3}, {%4,%5,%6,%7}, {%8,%9}, {%0,%1,%2,%3};"
        : "+f"(c[0]), "+f"(c[1]), "+f"(c[2]), "+f"(c[3])
        : "r"(a[0]), "r"(a[1]), "r"(a[2]), "r"(a[3]), "r"(b[0]), "r"(b[1]));
}
// pack: low half = lo, high half = hi
__device__ __forceinline__ uint32_t pack_bf2(float lo, float hi) {
    uint32_t r;
    asm("cvt.rn.bf16x2.f32 %0, %1, %2;" : "=r"(r) : "f"(hi), "f"(lo));
    return r;
}

// ---------------- fp32 -> bf16 hi/lo split (elementwise) --------------------
__global__ void __launch_bounds__(256) convert_split_kernel(
    const float* __restrict__ in, __nv_bfloat16* __restrict__ hi,
    __nv_bfloat16* __restrict__ lo)
{
    size_t i = (size_t)blockIdx.x * blockDim.x + threadIdx.x;
    float4 v = ((const float4*)in)[i];
    float vv[4] = {v.x, v.y, v.z, v.w};
    ushort4 h, l;
    unsigned short* hp = &h.x;
    unsigned short* lp = &l.x;
#pragma unroll
    for (int j = 0; j < 4; j++) {
        __nv_bfloat16 hb = __float2bfloat16_rn(vv[j]);
        float res = vv[j] - __bfloat162float(hb);
        __nv_bfloat16 lb = __float2bfloat16_rn(res);
        hp[j] = __bfloat16_as_ushort(hb);
        lp[j] = __bfloat16_as_ushort(lb);
    }
    ((ushort4*)hi)[i] = h;
    ((ushort4*)lo)[i] = l;
}

// ---------------- W[K,N] fp32 -> W^T[N,K] bf16 hi/lo (transpose + split) ----
__global__ void __launch_bounds__(256) wconvert_kernel(
    const float* __restrict__ W, __nv_bfloat16* __restrict__ Thi,
    __nv_bfloat16* __restrict__ Tlo)
{
    __shared__ float t[32][33];
    int n0 = blockIdx.x * 32;
    int k0 = blockIdx.y * 32;
    int x = threadIdx.x;
    int y = threadIdx.y;
#pragma unroll
    for (int r = y; r < 32; r += 8)
        t[r][x] = W[(size_t)(k0 + r) * DEMB + n0 + x];
    __syncthreads();
#pragma unroll
    for (int r = y; r < 32; r += 8) {
        float v = t[x][r];
        __nv_bfloat16 hb = __float2bfloat16_rn(v);
        float res = v - __bfloat162float(hb);
        __nv_bfloat16 lb = __float2bfloat16_rn(res);
        size_t o = (size_t)(n0 + r) * DEMB + k0 + x;
        Thi[o] = hb;
        Tlo[o] = lb;
    }
}

// ---------------- HMMA GEMM: C = A @ B^T + bias ------------------------------
// Output either fp32 (Cf) or bf16 hi/lo (Ch/Cl) when Cf == nullptr.
#define GBK  32
#define ASTR 40
#define TILEB (128 * ASTR * 2)
#define STAGEB (4 * TILEB)
#define GSMEM (2 * STAGEB)

__global__ void __launch_bounds__(256, 1) gemm_mma_kernel(
    const __nv_bfloat16* __restrict__ Ahi, const __nv_bfloat16* __restrict__ Alo,
    const __nv_bfloat16* __restrict__ Bhi, const __nv_bfloat16* __restrict__ Blo,
    const float* __restrict__ bias, float* __restrict__ Cf,
    __nv_bfloat16* __restrict__ Ch, __nv_bfloat16* __restrict__ Cl)
{
    extern __shared__ __align__(128) char smg[];
    const int tid  = threadIdx.x;
    const int wid  = tid >> 5;
    const int lane = tid & 31;
    const int bn = blockIdx.x;
    const int bm = blockIdx.y;
    const int wm = wid >> 2;
    const int wn = wid & 3;
    const uint32_t sbase = s2u(smg);

    const __nv_bfloat16* srcs[4] = {
        Ahi + (size_t)bm * 128 * DEMB, Alo + (size_t)bm * 128 * DEMB,
        Bhi + (size_t)bn * 128 * DEMB, Blo + (size_t)bn * 128 * DEMB };

    const int c0 = tid * 2;
    const int lr0 = c0 >> 2, lc0 = c0 & 3;
    const int lr1 = (c0 + 1) >> 2, lc1 = (c0 + 1) & 3;

    auto load_tile = [&](int stage, int k0) {
        uint32_t st = sbase + stage * STAGEB;
#pragma unroll
        for (int t = 0; t < 4; t++) {
            const __nv_bfloat16* src = srcs[t] + k0;
            uint32_t dst = st + t * TILEB;
            cp16(dst + (lr0 * ASTR + lc0 * 8) * 2, src + (size_t)lr0 * DEMB + lc0 * 8);
            cp16(dst + (lr1 * ASTR + lc1 * 8) * 2, src + (size_t)lr1 * DEMB + lc1 * 8);
        }
    };

    float acc[4][4][4];
#pragma unroll
    for (int mt = 0; mt < 4; mt++)
#pragma unroll
        for (int nt = 0; nt < 4; nt++)
#pragma unroll
            for (int e = 0; e < 4; e++) acc[mt][nt][e] = 0.0f;

    const int lr = lane & 7, sec = lane >> 3;
    const int a_row = (sec & 1) * 8 + lr;
    const int a_kof = (sec >> 1) * 8;
    const int b_row = (sec >> 1) * 8 + lr;
    const int b_kof = (sec & 1) * 8;

    load_tile(0, 0);
    cp_commit();

    const int NIT = DEMB / GBK;
    for (int i = 0; i < NIT; i++) {
        if (i + 1 < NIT) {
            load_tile((i + 1) & 1, (i + 1) * GBK);
            cp_commit();
            cp_wait<1>();
        } else {
            cp_wait<0>();
        }
        __syncthreads();

        uint32_t st = sbase + (i & 1) * STAGEB;
        uint32_t sAh = st, sAl = st + TILEB, sBh = st + 2 * TILEB, sBl = st + 3 * TILEB;

#pragma unroll
        for (int ks = 0; ks < 2; ks++) {
            uint32_t ah[4][4], al[4][4];
#pragma unroll
            for (int mt = 0; mt < 4; mt++) {
                uint32_t off = ((wm * 64 + mt * 16 + a_row) * ASTR + ks * 16 + a_kof) * 2;
                ldsm_x4(ah[mt], sAh + off);
                ldsm_x4(al[mt], sAl + off);
            }
            uint32_t bh[4][2], bl[4][2];
#pragma unroll
            for (int p = 0; p < 2; p++) {
                uint32_t off = ((wn * 32 + p * 16 + b_row) * ASTR + ks * 16 + b_kof) * 2;
                uint32_t r4[4];
                ldsm_x4(r4, sBh + off);
                bh[p * 2][0] = r4[0]; bh[p * 2][1] = r4[1];
                bh[p * 2 + 1][0] = r4[2]; bh[p * 2 + 1][1] = r4[3];
                ldsm_x4(r4, sBl + off);
                bl[p * 2][0] = r4[0]; bl[p * 2][1] = r4[1];
                bl[p * 2 + 1][0] = r4[2]; bl[p * 2 + 1][1] = r4[3];
            }
#pragma unroll
            for (int mt = 0; mt < 4; mt++)
#pragma unroll
                for (int nt = 0; nt < 4; nt++) {
                    mma16816(acc[mt][nt], ah[mt], bh[nt]);
                    mma16816(acc[mt][nt], ah[mt], bl[nt]);
                    mma16816(acc[mt][nt], al[mt], bh[nt]);
                }
        }
        __syncthreads();
    }

    const int g = lane >> 2;
    const int cc = (lane & 3) * 2;
#pragma unroll
    for (int mt = 0; mt < 4; mt++) {
        int row0 = bm * 128 + wm * 64 + mt * 16 + g;
#pragma unroll
        for (int nt = 0; nt < 4; nt++) {
            int col = bn * 128 + wn * 32 + nt * 8 + cc;
            float2 b2 = *(const float2*)(bias + col);
            float v0 = acc[mt][nt][0] + b2.x, v1 = acc[mt][nt][1] + b2.y;
            float v2 = acc[mt][nt][2] + b2.x, v3 = acc[mt][nt][3] + b2.y;
            if (Cf) {
                *(float2*)(Cf + (size_t)row0 * DEMB + col) = make_float2(v0, v1);
                *(float2*)(Cf + (size_t)(row0 + 8) * DEMB + col) = make_float2(v2, v3);
            } else {
                uint32_t h0 = pack_bf2(v0, v1);
                uint32_t h1 = pack_bf2(v2, v3);
                float r0 = v0 - __uint_as_float(h0 << 16);
                float r1 = v1 - __uint_as_float(h0 & 0xFFFF0000u);
                float r2 = v2 - __uint_as_float(h1 << 16);
                float r3 = v3 - __uint_as_float(h1 & 0xFFFF0000u);
                *(uint32_t*)(Ch + (size_t)row0 * DEMB + col) = h0;
                *(uint32_t*)(Ch + (size_t)(row0 + 8) * DEMB + col) = h1;
                *(uint32_t*)(Cl + (size_t)row0 * DEMB + col) = pack_bf2(r0, r1);
                *(uint32_t*)(Cl + (size_t)(row0 + 8) * DEMB + col) = pack_bf2(r2, r3);
            }
        }
    }
}

// ---------------- HMMA flash attention ---------------------------------------
// CTA: 256 q rows, one (batch, head). 8 warps x 32 q rows, full KV per warp.
// QK^T and PV both on tensor cores with bf16 hi/lo (3 passes each).
#define AQ   256
#define AKV  64
#define QSTR 72                               // smem row stride in bf16
#define QBYTES (AQ * QSTR * 2)                // 36864
#define KVT (AKV * QSTR * 2)                  // 9216
#define KVSTG (4 * KVT)                       // 36864
#define ASMEM (2 * QBYTES + 2 * KVSTG)        // 147456

__global__ void __launch_bounds__(256, 1) attn_mma_kernel(
    const __nv_bfloat16* __restrict__ Qh, const __nv_bfloat16* __restrict__ Ql,
    const __nv_bfloat16* __restrict__ Kh, const __nv_bfloat16* __restrict__ Kl,
    const __nv_bfloat16* __restrict__ Vh, const __nv_bfloat16* __restrict__ Vl,
    __nv_bfloat16* __restrict__ Oh, __nv_bfloat16* __restrict__ Ol)
{
    extern __shared__ __align__(128) char sma[];
    const int tid  = threadIdx.x;
    const int wid  = tid >> 5;
    const int lane = tid & 31;
    const int qb = blockIdx.x, h = blockIdx.y, b = blockIdx.z;

    const uint32_t sb  = s2u(sma);
    const uint32_t sQ0 = sb, sQ1 = sb + QBYTES;
    const uint32_t kvb = sb + 2 * QBYTES;

    const size_t hoff = (size_t)h * HDIM;
    const size_t qrow0 = (size_t)(b * SEQ + qb * AQ);
    const __nv_bfloat16* kvsrc[4] = {
        Kh + (size_t)(b * SEQ) * DEMB + hoff, Kl + (size_t)(b * SEQ) * DEMB + hoff,
        Vh + (size_t)(b * SEQ) * DEMB + hoff, Vl + (size_t)(b * SEQ) * DEMB + hoff };

    // ---- load Q (once) + KV stage 0, one cp.async group
#pragma unroll
    for (int i = 0; i < 16; i++) {
        int f = tid + i * 256;
        int arr = f >> 11;              // 0: hi, 1: lo
        int row = (f >> 3) & 255;
        int col = f & 7;
        const __nv_bfloat16* src =
            (arr ? Ql : Qh) + (qrow0 + row) * DEMB + hoff + col * 8;
        cp16((arr ? sQ1 : sQ0) + (row * QSTR + col * 8) * 2, src);
    }
    auto load_kv = [&](int stage, int kb) {
#pragma unroll
        for (int i = 0; i < 8; i++) {
            int f = tid + i * 256;
            int arr = f >> 9;           // 0..3: Kh,Kl,Vh,Vl
            int row = (f >> 3) & 63;
            int col = f & 7;
            cp16(kvb + stage * KVSTG + arr * KVT + (row * QSTR + col * 8) * 2,
                 kvsrc[arr] + (size_t)(kb + row) * DEMB + col * 8);
        }
    };
    load_kv(0, 0);
    cp_commit();

    // fragment lane mappings
    const int lr = lane & 7, sec = lane >> 3;
    const int a_row = (sec & 1) * 8 + lr;
    const int a_kof = (sec >> 1) * 8;
    const int b_row = (sec >> 1) * 8 + lr;     // K (non-trans): rows = kv
    const int b_kof = (sec & 1) * 8;
    const int v_row = (sec & 1) * 8 + lr;      // V (trans): rows = kv
    const int v_col = (sec >> 1) * 8;
    const int g = lane >> 2;

    float O[2][8][4];
    float m_r[2][2], l_r[2][2];
#pragma unroll
    for (int mt = 0; mt < 2; mt++) {
#pragma unroll
        for (int nt = 0; nt < 8; nt++)
#pragma unroll
            for (int e = 0; e < 4; e++) O[mt][nt][e] = 0.0f;
        m_r[mt][0] = m_r[mt][1] = -1e30f;
        l_r[mt][0] = l_r[mt][1] = 0.0f;
    }

    const int NB = SEQ / AKV;   // 32
    for (int i = 0; i < NB; i++) {
        if (i + 1 < NB) {
            load_kv((i + 1) & 1, (i + 1) * AKV);
            cp_commit();
            cp_wait<1>();
        } else {
            cp_wait<0>();
        }
        __syncthreads();

        uint32_t skh = kvb + (i & 1) * KVSTG;
        uint32_t skl = skh + KVT;
        uint32_t svh = skl + KVT;
        uint32_t svl = svh + KVT;

        // ---- S = Q K^T (hi/lo, 3 passes)
        float S[2][8][4];
#pragma unroll
        for (int mt = 0; mt < 2; mt++)
#pragma unroll
            for (int nt = 0; nt < 8; nt++)
#pragma unroll
                for (int e = 0; e < 4; e++) S[mt][nt][e] = 0.0f;

#pragma unroll
        for (int ks = 0; ks < 4; ks++) {
            uint32_t ah[2][4], al[2][4];
#pragma unroll
            for (int mt = 0; mt < 2; mt++) {
                uint32_t off = ((wid * 32 + mt * 16 + a_row) * QSTR + ks * 16 + a_kof) * 2;
                ldsm_x4(ah[mt], sQ0 + off);
                ldsm_x4(al[mt], sQ1 + off);
            }
#pragma unroll
            for (int ng = 0; ng < 4; ng++) {
                uint32_t bh[4], bl[4];
                uint32_t off = ((ng * 16 + b_row) * QSTR + ks * 16 + b_kof) * 2;
                ldsm_x4(bh, skh + off);
                ldsm_x4(bl, skl + off);
#pragma unroll
                for (int mt = 0; mt < 2; mt++) {
                    mma16816(S[mt][2 * ng],     ah[mt], &bh[0]);
                    mma16816(S[mt][2 * ng],     ah[mt], &bl[0]);
                    mma16816(S[mt][2 * ng],     al[mt], &bh[0]);
                    mma16816(S[mt][2 * ng + 1], ah[mt], &bh[2]);
                    mma16816(S[mt][2 * ng + 1], ah[mt], &bl[2]);
                    mma16816(S[mt][2 * ng + 1], al[mt], &bh[2]);
                }
            }
        }

        // ---- online softmax (warp-local; rows g, g+8 per m-tile)
#pragma unroll
        for (int mt = 0; mt < 2; mt++) {
#pragma unroll
            for (int hr = 0; hr < 2; hr++) {
                const int e0 = hr * 2;
                float mx = -1e30f;
#pragma unroll
                for (int nt = 0; nt < 8; nt++) {
                    S[mt][nt][e0]     *= 0.125f;
                    S[mt][nt][e0 + 1] *= 0.125f;
                    mx = fmaxf(mx, fmaxf(S[mt][nt][e0], S[mt][nt][e0 + 1]));
                }
                mx = fmaxf(mx, __shfl_xor_sync(0xffffffffu, mx, 1));
                mx = fmaxf(mx, __shfl_xor_sync(0xffffffffu, mx, 2));
                float mnew = fmaxf(m_r[mt][hr], mx);
                float corr = __expf(m_r[mt][hr] - mnew);
                float sum = 0.0f;
#pragma unroll
                for (int nt = 0; nt < 8; nt++) {
                    float p0 = __expf(S[mt][nt][e0] - mnew);
                    float p1 = __expf(S[mt][nt][e0 + 1] - mnew);
                    S[mt][nt][e0] = p0; S[mt][nt][e0 + 1] = p1;
                    sum += p0 + p1;
                }
                sum += __shfl_xor_sync(0xffffffffu, sum, 1);
                sum += __shfl_xor_sync(0xffffffffu, sum, 2);
                l_r[mt][hr] = l_r[mt][hr] * corr + sum;
                m_r[mt][hr] = mnew;
#pragma unroll
                for (int nt = 0; nt < 8; nt++) {
                    O[mt][nt][e0]     *= corr;
                    O[mt][nt][e0 + 1] *= corr;
                }
            }
        }

        // ---- O += P V (P from regs as A-frags, hi/lo; V via ldmatrix.trans)
#pragma unroll
        for (int ks = 0; ks < 4; ks++) {
            uint32_t ph[2][4], pl[2][4];
#pragma unroll
            for (int mt = 0; mt < 2; mt++) {
#pragma unroll
                for (int j = 0; j < 2; j++) {       // n-tiles 2ks, 2ks+1
                    const float* sp = S[mt][2 * ks + j];
                    uint32_t h01 = pack_bf2(sp[0], sp[1]);
                    uint32_t h23 = pack_bf2(sp[2], sp[3]);
                    ph[mt][2 * j]     = h01;
                    ph[mt][2 * j + 1] = h23;
                    float r0 = sp[0] - __uint_as_float(h01 << 16);
                    float r1 = sp[1] - __uint_as_float(h01 & 0xFFFF0000u);
                    float r2 = sp[2] - __uint_as_float(h23 << 16);
                    float r3 = sp[3] - __uint_as_float(h23 & 0xFFFF0000u);
                    pl[mt][2 * j]     = pack_bf2(r0, r1);
                    pl[mt][2 * j + 1] = pack_bf2(r2, r3);
                }
                // reorder: a-frag = {t(2ks) c0c1, t(2ks) c2c3, t(2ks+1) c0c1, t(2ks+1) c2c3}
                // built above in exactly that order: ph[mt] = {h01_j0, h23_j0, h01_j1, h23_j1}
            }
#pragma unroll
            for (int dg = 0; dg < 4; dg++) {
                uint32_t vh[4], vl[4];
                uint32_t off = ((ks * 16 + v_row) * QSTR + dg * 16 + v_col) * 2;
                ldsm_x4t(vh, svh + off);
                ldsm_x4t(vl, svl + off);
#pragma unroll
                for (int mt = 0; mt < 2; mt++) {
                    mma16816(O[mt][2 * dg],     ph[mt], &vh[0]);
                    mma16816(O[mt][2 * dg],     ph[mt], &vl[0]);
                    mma16816(O[mt][2 * dg],     pl[mt], &vh[0]);
                    mma16816(O[mt][2 * dg + 1], ph[mt], &vh[2]);
                    mma16816(O[mt][2 * dg + 1], ph[mt], &vl[2]);
                    mma16816(O[mt][2 * dg + 1], pl[mt], &vh[2]);
                }
            }
        }
        __syncthreads();
    }

    // ---- normalize + split to bf16 hi/lo + store (O layout: [B,S,H*D] merge)
    const int t2 = (lane & 3) * 2;
#pragma unroll
    for (int mt = 0; mt < 2; mt++) {
#pragma unroll
        for (int hr = 0; hr < 2; hr++) {
            float inv = 1.0f / l_r[mt][hr];
            size_t row = qrow0 + wid * 32 + mt * 16 + g + hr * 8;
#pragma unroll
            for (int nt = 0; nt < 8; nt++) {
                float o0 = O[mt][nt][2 * hr]     * inv;
                float o1 = O[mt][nt][2 * hr + 1] * inv;
                uint32_t hb = pack_bf2(o0, o1);
                float r0 = o0 - __uint_as_float(hb << 16);
                float r1 = o1 - __uint_as_float(hb & 0xFFFF0000u);
                size_t off = row * DEMB + hoff + nt * 8 + t2;
                *(uint32_t*)(Oh + off) = hb;
                *(uint32_t*)(Ol + off) = pack_bf2(r0, r1);
            }
        }
    }
}

// ---------------- launch -----------------------------------------------------
extern "C" void kernel_launch(void* const* d_in, const int* in_sizes, int n_in,
                              void* d_out, int out_size)
{
    const float* x  = (const float*)d_in[0];
    const float* qw = (const float*)d_in[1];
    const float* qb = (const float*)d_in[2];
    const float* kw = (const float*)d_in[3];
    const float* kb = (const float*)d_in[4];
    const float* vw = (const float*)d_in[5];
    const float* vb = (const float*)d_in[6];
    const float* ow = (const float*)d_in[7];
    const float* ob = (const float*)d_in[8];
    float* out = (float*)d_out;

    __nv_bfloat16 *xh, *xl, *wth, *wtl, *qh, *ql, *kh, *kl, *vh, *vl;
    cudaGetSymbolAddress((void**)&xh, g_xhi);
    cudaGetSymbolAddress((void**)&xl, g_xlo);
    cudaGetSymbolAddress((void**)&wth, g_wthi);
    cudaGetSymbolAddress((void**)&wtl, g_wtlo);
    cudaGetSymbolAddress((void**)&qh, g_qh);
    cudaGetSymbolAddress((void**)&ql, g_ql);
    cudaGetSymbolAddress((void**)&kh, g_kh);
    cudaGetSymbolAddress((void**)&kl, g_kl);
    cudaGetSymbolAddress((void**)&vh, g_vh);
    cudaGetSymbolAddress((void**)&vl, g_vl);

    cudaFuncSetAttribute(gemm_mma_kernel, cudaFuncAttributeMaxDynamicSharedMemorySize,
                         GSMEM);
    cudaFuncSetAttribute(attn_mma_kernel, cudaFuncAttributeMaxDynamicSharedMemorySize,
                         ASMEM);

    const size_t WSZ = (size_t)DEMB * DEMB;
    dim3 wgrid(32, 32), wblk(32, 8);
    dim3 ggrid(DEMB / 128, MROWS / 128);   // (8, 64)

    convert_split_kernel<<<MROWS * DEMB / 4 / 256, 256>>>(x, xh, xl);
    wconvert_kernel<<<wgrid, wblk>>>(qw, wth + 0 * WSZ, wtl + 0 * WSZ);
    wconvert_kernel<<<wgrid, wblk>>>(kw, wth + 1 * WSZ, wtl + 1 * WSZ);
    wconvert_kernel<<<wgrid, wblk>>>(vw, wth + 2 * WSZ, wtl + 2 * WSZ);
    wconvert_kernel<<<wgrid, wblk>>>(ow, wth + 3 * WSZ, wtl + 3 * WSZ);

    // projections: bf16 hi/lo outputs
    gemm_mma_kernel<<<ggrid, 256, GSMEM>>>(xh, xl, wth + 0 * WSZ, wtl + 0 * WSZ,
                                           qb, nullptr, qh, ql);
    gemm_mma_kernel<<<ggrid, 256, GSMEM>>>(xh, xl, wth + 1 * WSZ, wtl + 1 * WSZ,
                                           kb, nullptr, kh, kl);
    gemm_mma_kernel<<<ggrid, 256, GSMEM>>>(xh, xl, wth + 2 * WSZ, wtl + 2 * WSZ,
                                           vb, nullptr, vh, vl);

    // attention writes its bf16 hi/lo output into xh/xl (x split no longer needed)
    dim3 attn_grid(SEQ / AQ, NHEADS, BATCH);   // (8, 16, 4)
    attn_mma_kernel<<<attn_grid, 256, ASMEM>>>(qh, ql, kh, kl, vh, vl, xh, xl);

    // output projection: fp32 out
    gemm_mma_kernel<<<ggrid, 256, GSMEM>>>(xh, xl, wth + 3 * WSZ, wtl + 3 * WSZ,
                                           ob, out, nullptr, nullptr);
}

// round 5
// speedup vs baseline: 2.7242x; 1.0506x over previous
#include <cuda_runtime.h>
#include <cuda_bf16.h>
#include <cstdint>

// Problem constants
#define BATCH   4
#define SEQ     2048
#define DEMB    1024
#define NHEADS  16
#define HDIM    64
#define MROWS   (BATCH * SEQ)   // 8192

// ---------------- scratch (device globals) -----------------------------------
__device__ __nv_bfloat16 g_xhi[(size_t)MROWS * DEMB];
__device__ __nv_bfloat16 g_xlo[(size_t)MROWS * DEMB];
__device__ __nv_bfloat16 g_qh[(size_t)MROWS * DEMB];
__device__ __nv_bfloat16 g_ql[(size_t)MROWS * DEMB];
__device__ __nv_bfloat16 g_kh[(size_t)MROWS * DEMB];
__device__ __nv_bfloat16 g_kl[(size_t)MROWS * DEMB];
__device__ __nv_bfloat16 g_vh[(size_t)MROWS * DEMB];
__device__ __nv_bfloat16 g_vl[(size_t)MROWS * DEMB];
__device__ __nv_bfloat16 g_wthi[(size_t)4 * DEMB * DEMB];
__device__ __nv_bfloat16 g_wtlo[(size_t)4 * DEMB * DEMB];

// ---------------- helpers -----------------------------------------------------
__device__ __forceinline__ uint32_t s2u(const void* p) {
    uint32_t a;
    asm("{ .reg .u64 t; cvta.to.shared.u64 t, %1; cvt.u32.u64 %0, t; }"
        : "=r"(a) : "l"(p));
    return a;
}
__device__ __forceinline__ void cp16(uint32_t dst, const void* src) {
    asm volatile("cp.async.cg.shared.global [%0], [%1], 16;"
                 :: "r"(dst), "l"(src));
}
__device__ __forceinline__ void cp_commit() {
    asm volatile("cp.async.commit_group;");
}
template <int N>
__device__ __forceinline__ void cp_wait() {
    asm volatile("cp.async.wait_group %0;" :: "n"(N));
}
__device__ __forceinline__ void ldsm_x4(uint32_t* r, uint32_t addr) {
    asm volatile("ldmatrix.sync.aligned.m8n8.x4.shared.b16 {%0,%1,%2,%3}, [%4];"
                 : "=r"(r[0]), "=r"(r[1]), "=r"(r[2]), "=r"(r[3]) : "r"(addr));
}
__device__ __forceinline__ void ldsm_x4t(uint32_t* r, uint32_t addr) {
    asm volatile("ldmatrix.sync.aligned.m8n8.x4.trans.shared.b16 {%0,%1,%2,%3}, [%4];"
                 : "=r"(r[0]), "=r"(r[1]), "=r"(r[2]), "=r"(r[3]) : "r"(addr));
}
__device__ __forceinline__ void mma16816(float* c, const uint32_t* a,
                                         const uint32_t* b) {
    asm volatile(
        "mma.sync.aligned.m16n8k16.row.col.f32.bf16.bf16.f32 "
        "{%0,%1,%2,%3}, {%4,%5,%6,%7}, {%8,%9}, {%0,%1,%2,%3};"
        : "+f"(c[0]), "+f"(c[1]), "+f"(c[2]), "+f"(c[3])
        : "r"(a[0]), "r"(a[1]), "r"(a[2]), "r"(a[3]), "r"(b[0]), "r"(b[1]));
}
__device__ __forceinline__ uint32_t pack_bf2(float lo, float hi) {
    uint32_t r;
    asm("cvt.rn.bf16x2.f32 %0, %1, %2;" : "=r"(r) : "f"(hi), "f"(lo));
    return r;
}

// ---------------- fp32 -> bf16 hi/lo split (elementwise) --------------------
__global__ void __launch_bounds__(256) convert_split_kernel(
    const float* __restrict__ in, __nv_bfloat16* __restrict__ hi,
    __nv_bfloat16* __restrict__ lo)
{
    size_t i = (size_t)blockIdx.x * blockDim.x + threadIdx.x;
    float4 v = ((const float4*)in)[i];
    float vv[4] = {v.x, v.y, v.z, v.w};
    ushort4 h, l;
    unsigned short* hp = &h.x;
    unsigned short* lp = &l.x;
#pragma unroll
    for (int j = 0; j < 4; j++) {
        __nv_bfloat16 hb = __float2bfloat16_rn(vv[j]);
        float res = vv[j] - __bfloat162float(hb);
        __nv_bfloat16 lb = __float2bfloat16_rn(res);
        hp[j] = __bfloat16_as_ushort(hb);
        lp[j] = __bfloat16_as_ushort(lb);
    }
    ((ushort4*)hi)[i] = h;
    ((ushort4*)lo)[i] = l;
}

// ---------------- W[K,N] fp32 -> W^T[N,K] bf16 hi/lo (transpose + split) ----
__global__ void __launch_bounds__(256) wconvert_kernel(
    const float* __restrict__ W, __nv_bfloat16* __restrict__ Thi,
    __nv_bfloat16* __restrict__ Tlo)
{
    __shared__ float t[32][33];
    int n0 = blockIdx.x * 32;
    int k0 = blockIdx.y * 32;
    int x = threadIdx.x;
    int y = threadIdx.y;
#pragma unroll
    for (int r = y; r < 32; r += 8)
        t[r][x] = W[(size_t)(k0 + r) * DEMB + n0 + x];
    __syncthreads();
#pragma unroll
    for (int r = y; r < 32; r += 8) {
        float v = t[x][r];
        __nv_bfloat16 hb = __float2bfloat16_rn(v);
        float res = v - __bfloat162float(hb);
        __nv_bfloat16 lb = __float2bfloat16_rn(res);
        size_t o = (size_t)(n0 + r) * DEMB + k0 + x;
        Thi[o] = hb;
        Tlo[o] = lb;
    }
}

// ---------------- HMMA GEMM v2: 256x128 CTA tile, QKV-fused ------------------
// A: bf16 hi/lo [M,K]; weights: bf16 hi/lo [N,K], 3 matrices contiguous.
// blockIdx.x: 0..23 (QKV) or 0..7 (single). wsel = bn>>3 selects weight/out.
// If Cf != null (single-matrix mode): fp32 out with bias b0.
#define GBK   32
#define GASTR 40                               // smem row stride (bf16)
#define ATILE (256 * GASTR * 2)                // 20480 B per A array
#define BTILE (128 * GASTR * 2)                // 10240 B per B array
#define STAGEB (2 * ATILE + 2 * BTILE)         // 61440
#define GSMEM (2 * STAGEB)                     // 122880

__global__ void __launch_bounds__(256, 1) gemm256_kernel(
    const __nv_bfloat16* __restrict__ Ahi, const __nv_bfloat16* __restrict__ Alo,
    const __nv_bfloat16* __restrict__ Wh,  const __nv_bfloat16* __restrict__ Wl,
    const float* __restrict__ b0, const float* __restrict__ b1,
    const float* __restrict__ b2,
    float* __restrict__ Cf,
    __nv_bfloat16* __restrict__ h0, __nv_bfloat16* __restrict__ l0,
    __nv_bfloat16* __restrict__ h1, __nv_bfloat16* __restrict__ l1,
    __nv_bfloat16* __restrict__ h2, __nv_bfloat16* __restrict__ l2)
{
    extern __shared__ __align__(128) char smg[];
    const int tid  = threadIdx.x;
    const int wid  = tid >> 5;
    const int lane = tid & 31;
    const int bnx = blockIdx.x;
    const int bm  = blockIdx.y;
    const int wsel = bnx >> 3;
    const int bn   = bnx & 7;
    const int wm = wid & 3;                  // 0..3 -> m offset
    const int wn = wid >> 2;                 // 0..1 -> n offset
    const uint32_t sb = s2u(smg);

    const size_t WSZ = (size_t)DEMB * DEMB;
    const __nv_bfloat16* Asrc[2] = {
        Ahi + (size_t)bm * 256 * DEMB, Alo + (size_t)bm * 256 * DEMB };
    const __nv_bfloat16* Bsrc[2] = {
        Wh + wsel * WSZ + (size_t)bn * 128 * DEMB,
        Wl + wsel * WSZ + (size_t)bn * 128 * DEMB };
    const float* bias = wsel == 0 ? b0 : (wsel == 1 ? b1 : b2);
    __nv_bfloat16* Ch = wsel == 0 ? h0 : (wsel == 1 ? h1 : h2);
    __nv_bfloat16* Cl = wsel == 0 ? l0 : (wsel == 1 ? l1 : l2);

    // load mapping (per thread, 12 cp16: 8 for A-pair, 4 for B-pair)
    auto load_tile = [&](int stage, int k0) {
        uint32_t st = sb + stage * STAGEB;
#pragma unroll
        for (int i = 0; i < 8; i++) {
            int f = i * 256 + tid;            // 0..2047
            int arr = f >> 10;
            int rem = f & 1023;
            int row = rem >> 2, kc = rem & 3;
            cp16(st + arr * ATILE + (row * GASTR + kc * 8) * 2,
                 Asrc[arr] + (size_t)row * DEMB + k0 + kc * 8);
        }
#pragma unroll
        for (int i = 0; i < 4; i++) {
            int f = i * 256 + tid;            // 0..1023
            int arr = f >> 9;
            int rem = f & 511;
            int row = rem >> 2, kc = rem & 3;
            cp16(st + 2 * ATILE + arr * BTILE + (row * GASTR + kc * 8) * 2,
                 Bsrc[arr] + (size_t)row * DEMB + k0 + kc * 8);
        }
    };

    float acc[4][8][4];
#pragma unroll
    for (int mt = 0; mt < 4; mt++)
#pragma unroll
        for (int nt = 0; nt < 8; nt++)
#pragma unroll
            for (int e = 0; e < 4; e++) acc[mt][nt][e] = 0.0f;

    const int lr = lane & 7, sec = lane >> 3;
    const int a_row = (sec & 1) * 8 + lr;
    const int a_kof = (sec >> 1) * 8;
    const int b_row = (sec >> 1) * 8 + lr;
    const int b_kof = (sec & 1) * 8;

    load_tile(0, 0);
    cp_commit();

    const int NIT = DEMB / GBK;   // 32
    for (int i = 0; i < NIT; i++) {
        if (i + 1 < NIT) {
            load_tile((i + 1) & 1, (i + 1) * GBK);
            cp_commit();
            cp_wait<1>();
        } else {
            cp_wait<0>();
        }
        __syncthreads();

        uint32_t st  = sb + (i & 1) * STAGEB;
        uint32_t sAh = st, sAl = st + ATILE;
        uint32_t sBh = st + 2 * ATILE, sBl = sBh + BTILE;

#pragma unroll
        for (int ks = 0; ks < 2; ks++) {
            uint32_t ah[4][4], al[4][4];
#pragma unroll
            for (int mt = 0; mt < 4; mt++) {
                uint32_t off = ((wm * 64 + mt * 16 + a_row) * GASTR
                                + ks * 16 + a_kof) * 2;
                ldsm_x4(ah[mt], sAh + off);
                ldsm_x4(al[mt], sAl + off);
            }
#pragma unroll
            for (int p = 0; p < 4; p++) {     // each p covers n-tiles 2p, 2p+1
                uint32_t off = ((wn * 64 + p * 16 + b_row) * GASTR
                                + ks * 16 + b_kof) * 2;
                uint32_t bh[4], bl[4];
                ldsm_x4(bh, sBh + off);
                ldsm_x4(bl, sBl + off);
#pragma unroll
                for (int mt = 0; mt < 4; mt++) {
                    mma16816(acc[mt][2 * p],     ah[mt], &bh[0]);
                    mma16816(acc[mt][2 * p],     ah[mt], &bl[0]);
                    mma16816(acc[mt][2 * p],     al[mt], &bh[0]);
                    mma16816(acc[mt][2 * p + 1], ah[mt], &bh[2]);
                    mma16816(acc[mt][2 * p + 1], ah[mt], &bl[2]);
                    mma16816(acc[mt][2 * p + 1], al[mt], &bh[2]);
                }
            }
        }
        __syncthreads();
    }

    // epilogue
    const int g  = lane >> 2;
    const int cc = (lane & 3) * 2;
#pragma unroll
    for (int mt = 0; mt < 4; mt++) {
        int row0 = bm * 256 + wm * 64 + mt * 16 + g;
#pragma unroll
        for (int nt = 0; nt < 8; nt++) {
            int col = bn * 128 + wn * 64 + nt * 8 + cc;
            float2 b2v = *(const float2*)(bias + col);
            float v0 = acc[mt][nt][0] + b2v.x, v1 = acc[mt][nt][1] + b2v.y;
            float v2 = acc[mt][nt][2] + b2v.x, v3 = acc[mt][nt][3] + b2v.y;
            if (Cf) {
                *(float2*)(Cf + (size_t)row0 * DEMB + col) = make_float2(v0, v1);
                *(float2*)(Cf + (size_t)(row0 + 8) * DEMB + col) = make_float2(v2, v3);
            } else {
                uint32_t hh0 = pack_bf2(v0, v1);
                uint32_t hh1 = pack_bf2(v2, v3);
                float r0 = v0 - __uint_as_float(hh0 << 16);
                float r1 = v1 - __uint_as_float(hh0 & 0xFFFF0000u);
                float r2 = v2 - __uint_as_float(hh1 << 16);
                float r3 = v3 - __uint_as_float(hh1 & 0xFFFF0000u);
                *(uint32_t*)(Ch + (size_t)row0 * DEMB + col) = hh0;
                *(uint32_t*)(Ch + (size_t)(row0 + 8) * DEMB + col) = hh1;
                *(uint32_t*)(Cl + (size_t)row0 * DEMB + col) = pack_bf2(r0, r1);
                *(uint32_t*)(Cl + (size_t)(row0 + 8) * DEMB + col) = pack_bf2(r2, r3);
            }
        }
    }
}

// ---------------- HMMA flash attention (unchanged from R4) -------------------
#define AQ   256
#define AKV  64
#define QSTR 72
#define QBYTES (AQ * QSTR * 2)
#define KVT (AKV * QSTR * 2)
#define KVSTG (4 * KVT)
#define ASMEM (2 * QBYTES + 2 * KVSTG)

__global__ void __launch_bounds__(256, 1) attn_mma_kernel(
    const __nv_bfloat16* __restrict__ Qh, const __nv_bfloat16* __restrict__ Ql,
    const __nv_bfloat16* __restrict__ Kh, const __nv_bfloat16* __restrict__ Kl,
    const __nv_bfloat16* __restrict__ Vh, const __nv_bfloat16* __restrict__ Vl,
    __nv_bfloat16* __restrict__ Oh, __nv_bfloat16* __restrict__ Ol)
{
    extern __shared__ __align__(128) char sma[];
    const int tid  = threadIdx.x;
    const int wid  = tid >> 5;
    const int lane = tid & 31;
    const int qb = blockIdx.x, h = blockIdx.y, b = blockIdx.z;

    const uint32_t sb  = s2u(sma);
    const uint32_t sQ0 = sb, sQ1 = sb + QBYTES;
    const uint32_t kvb = sb + 2 * QBYTES;

    const size_t hoff = (size_t)h * HDIM;
    const size_t qrow0 = (size_t)(b * SEQ + qb * AQ);
    const __nv_bfloat16* kvsrc[4] = {
        Kh + (size_t)(b * SEQ) * DEMB + hoff, Kl + (size_t)(b * SEQ) * DEMB + hoff,
        Vh + (size_t)(b * SEQ) * DEMB + hoff, Vl + (size_t)(b * SEQ) * DEMB + hoff };

#pragma unroll
    for (int i = 0; i < 16; i++) {
        int f = tid + i * 256;
        int arr = f >> 11;
        int row = (f >> 3) & 255;
        int col = f & 7;
        const __nv_bfloat16* src =
            (arr ? Ql : Qh) + (qrow0 + row) * DEMB + hoff + col * 8;
        cp16((arr ? sQ1 : sQ0) + (row * QSTR + col * 8) * 2, src);
    }
    auto load_kv = [&](int stage, int kb) {
#pragma unroll
        for (int i = 0; i < 8; i++) {
            int f = tid + i * 256;
            int arr = f >> 9;
            int row = (f >> 3) & 63;
            int col = f & 7;
            cp16(kvb + stage * KVSTG + arr * KVT + (row * QSTR + col * 8) * 2,
                 kvsrc[arr] + (size_t)(kb + row) * DEMB + col * 8);
        }
    };
    load_kv(0, 0);
    cp_commit();

    const int lr = lane & 7, sec = lane >> 3;
    const int a_row = (sec & 1) * 8 + lr;
    const int a_kof = (sec >> 1) * 8;
    const int b_row = (sec >> 1) * 8 + lr;
    const int b_kof = (sec & 1) * 8;
    const int v_row = (sec & 1) * 8 + lr;
    const int v_col = (sec >> 1) * 8;
    const int g = lane >> 2;

    float O[2][8][4];
    float m_r[2][2], l_r[2][2];
#pragma unroll
    for (int mt = 0; mt < 2; mt++) {
#pragma unroll
        for (int nt = 0; nt < 8; nt++)
#pragma unroll
            for (int e = 0; e < 4; e++) O[mt][nt][e] = 0.0f;
        m_r[mt][0] = m_r[mt][1] = -1e30f;
        l_r[mt][0] = l_r[mt][1] = 0.0f;
    }

    const int NB = SEQ / AKV;
    for (int i = 0; i < NB; i++) {
        if (i + 1 < NB) {
            load_kv((i + 1) & 1, (i + 1) * AKV);
            cp_commit();
            cp_wait<1>();
        } else {
            cp_wait<0>();
        }
        __syncthreads();

        uint32_t skh = kvb + (i & 1) * KVSTG;
        uint32_t skl = skh + KVT;
        uint32_t svh = skl + KVT;
        uint32_t svl = svh + KVT;

        float S[2][8][4];
#pragma unroll
        for (int mt = 0; mt < 2; mt++)
#pragma unroll
            for (int nt = 0; nt < 8; nt++)
#pragma unroll
                for (int e = 0; e < 4; e++) S[mt][nt][e] = 0.0f;

#pragma unroll
        for (int ks = 0; ks < 4; ks++) {
            uint32_t ah[2][4], al[2][4];
#pragma unroll
            for (int mt = 0; mt < 2; mt++) {
                uint32_t off = ((wid * 32 + mt * 16 + a_row) * QSTR + ks * 16 + a_kof) * 2;
                ldsm_x4(ah[mt], sQ0 + off);
                ldsm_x4(al[mt], sQ1 + off);
            }
#pragma unroll
            for (int ng = 0; ng < 4; ng++) {
                uint32_t bh[4], bl[4];
                uint32_t off = ((ng * 16 + b_row) * QSTR + ks * 16 + b_kof) * 2;
                ldsm_x4(bh, skh + off);
                ldsm_x4(bl, skl + off);
#pragma unroll
                for (int mt = 0; mt < 2; mt++) {
                    mma16816(S[mt][2 * ng],     ah[mt], &bh[0]);
                    mma16816(S[mt][2 * ng],     ah[mt], &bl[0]);
                    mma16816(S[mt][2 * ng],     al[mt], &bh[0]);
                    mma16816(S[mt][2 * ng + 1], ah[mt], &bh[2]);
                    mma16816(S[mt][2 * ng + 1], ah[mt], &bl[2]);
                    mma16816(S[mt][2 * ng + 1], al[mt], &bh[2]);
                }
            }
        }

#pragma unroll
        for (int mt = 0; mt < 2; mt++) {
#pragma unroll
            for (int hr = 0; hr < 2; hr++) {
                const int e0 = hr * 2;
                float mx = -1e30f;
#pragma unroll
                for (int nt = 0; nt < 8; nt++) {
                    S[mt][nt][e0]     *= 0.125f;
                    S[mt][nt][e0 + 1] *= 0.125f;
                    mx = fmaxf(mx, fmaxf(S[mt][nt][e0], S[mt][nt][e0 + 1]));
                }
                mx = fmaxf(mx, __shfl_xor_sync(0xffffffffu, mx, 1));
                mx = fmaxf(mx, __shfl_xor_sync(0xffffffffu, mx, 2));
                float mnew = fmaxf(m_r[mt][hr], mx);
                float corr = __expf(m_r[mt][hr] - mnew);
                float sum = 0.0f;
#pragma unroll
                for (int nt = 0; nt < 8; nt++) {
                    float p0 = __expf(S[mt][nt][e0] - mnew);
                    float p1 = __expf(S[mt][nt][e0 + 1] - mnew);
                    S[mt][nt][e0] = p0; S[mt][nt][e0 + 1] = p1;
                    sum += p0 + p1;
                }
                sum += __shfl_xor_sync(0xffffffffu, sum, 1);
                sum += __shfl_xor_sync(0xffffffffu, sum, 2);
                l_r[mt][hr] = l_r[mt][hr] * corr + sum;
                m_r[mt][hr] = mnew;
#pragma unroll
                for (int nt = 0; nt < 8; nt++) {
                    O[mt][nt][e0]     *= corr;
                    O[mt][nt][e0 + 1] *= corr;
                }
            }
        }

#pragma unroll
        for (int ks = 0; ks < 4; ks++) {
            uint32_t ph[2][4], pl[2][4];
#pragma unroll
            for (int mt = 0; mt < 2; mt++) {
#pragma unroll
                for (int j = 0; j < 2; j++) {
                    const float* sp = S[mt][2 * ks + j];
                    uint32_t h01 = pack_bf2(sp[0], sp[1]);
                    uint32_t h23 = pack_bf2(sp[2], sp[3]);
                    ph[mt][2 * j]     = h01;
                    ph[mt][2 * j + 1] = h23;
                    float r0 = sp[0] - __uint_as_float(h01 << 16);
                    float r1 = sp[1] - __uint_as_float(h01 & 0xFFFF0000u);
                    float r2 = sp[2] - __uint_as_float(h23 << 16);
                    float r3 = sp[3] - __uint_as_float(h23 & 0xFFFF0000u);
                    pl[mt][2 * j]     = pack_bf2(r0, r1);
                    pl[mt][2 * j + 1] = pack_bf2(r2, r3);
                }
            }
#pragma unroll
            for (int dg = 0; dg < 4; dg++) {
                uint32_t vh[4], vl[4];
                uint32_t off = ((ks * 16 + v_row) * QSTR + dg * 16 + v_col) * 2;
                ldsm_x4t(vh, svh + off);
                ldsm_x4t(vl, svl + off);
#pragma unroll
                for (int mt = 0; mt < 2; mt++) {
                    mma16816(O[mt][2 * dg],     ph[mt], &vh[0]);
                    mma16816(O[mt][2 * dg],     ph[mt], &vl[0]);
                    mma16816(O[mt][2 * dg],     pl[mt], &vh[0]);
                    mma16816(O[mt][2 * dg + 1], ph[mt], &vh[2]);
                    mma16816(O[mt][2 * dg + 1], ph[mt], &vl[2]);
                    mma16816(O[mt][2 * dg + 1], pl[mt], &vh[2]);
                }
            }
        }
        __syncthreads();
    }

    const int t2 = (lane & 3) * 2;
#pragma unroll
    for (int mt = 0; mt < 2; mt++) {
#pragma unroll
        for (int hr = 0; hr < 2; hr++) {
            float inv = 1.0f / l_r[mt][hr];
            size_t row = qrow0 + wid * 32 + mt * 16 + g + hr * 8;
#pragma unroll
            for (int nt = 0; nt < 8; nt++) {
                float o0 = O[mt][nt][2 * hr]     * inv;
                float o1 = O[mt][nt][2 * hr + 1] * inv;
                uint32_t hb = pack_bf2(o0, o1);
                float r0 = o0 - __uint_as_float(hb << 16);
                float r1 = o1 - __uint_as_float(hb & 0xFFFF0000u);
                size_t off = row * DEMB + hoff + nt * 8 + t2;
                *(uint32_t*)(Oh + off) = hb;
                *(uint32_t*)(Ol + off) = pack_bf2(r0, r1);
            }
        }
    }
}

// ---------------- launch -----------------------------------------------------
extern "C" void kernel_launch(void* const* d_in, const int* in_sizes, int n_in,
                              void* d_out, int out_size)
{
    const float* x  = (const float*)d_in[0];
    const float* qw = (const float*)d_in[1];
    const float* qb = (const float*)d_in[2];
    const float* kw = (const float*)d_in[3];
    const float* kb = (const float*)d_in[4];
    const float* vw = (const float*)d_in[5];
    const float* vb = (const float*)d_in[6];
    const float* ow = (const float*)d_in[7];
    const float* ob = (const float*)d_in[8];
    float* out = (float*)d_out;

    __nv_bfloat16 *xh, *xl, *wth, *wtl, *qh, *ql, *kh, *kl, *vh, *vl;
    cudaGetSymbolAddress((void**)&xh, g_xhi);
    cudaGetSymbolAddress((void**)&xl, g_xlo);
    cudaGetSymbolAddress((void**)&wth, g_wthi);
    cudaGetSymbolAddress((void**)&wtl, g_wtlo);
    cudaGetSymbolAddress((void**)&qh, g_qh);
    cudaGetSymbolAddress((void**)&ql, g_ql);
    cudaGetSymbolAddress((void**)&kh, g_kh);
    cudaGetSymbolAddress((void**)&kl, g_kl);
    cudaGetSymbolAddress((void**)&vh, g_vh);
    cudaGetSymbolAddress((void**)&vl, g_vl);

    cudaFuncSetAttribute(gemm256_kernel, cudaFuncAttributeMaxDynamicSharedMemorySize,
                         GSMEM);
    cudaFuncSetAttribute(attn_mma_kernel, cudaFuncAttributeMaxDynamicSharedMemorySize,
                         ASMEM);

    const size_t WSZ = (size_t)DEMB * DEMB;
    dim3 wgrid(32, 32), wblk(32, 8);

    convert_split_kernel<<<MROWS * DEMB / 4 / 256, 256>>>(x, xh, xl);
    wconvert_kernel<<<wgrid, wblk>>>(qw, wth + 0 * WSZ, wtl + 0 * WSZ);
    wconvert_kernel<<<wgrid, wblk>>>(kw, wth + 1 * WSZ, wtl + 1 * WSZ);
    wconvert_kernel<<<wgrid, wblk>>>(vw, wth + 2 * WSZ, wtl + 2 * WSZ);
    wconvert_kernel<<<wgrid, wblk>>>(ow, wth + 3 * WSZ, wtl + 3 * WSZ);

    // fused QKV projection: grid x = 24 (3 weights x 8 n-tiles), y = 32 m-tiles
    dim3 qkv_grid(24, MROWS / 256);
    gemm256_kernel<<<qkv_grid, 256, GSMEM>>>(
        xh, xl, wth, wtl, qb, kb, vb,
        nullptr, qh, ql, kh, kl, vh, vl);

    dim3 attn_grid(SEQ / AQ, NHEADS, BATCH);
    attn_mma_kernel<<<attn_grid, 256, ASMEM>>>(qh, ql, kh, kl, vh, vl, xh, xl);

    // output projection: single-matrix fp32 mode (weight index 3)
    dim3 o_grid(8, MROWS / 256);
    gemm256_kernel<<<o_grid, 256, GSMEM>>>(
        xh, xl, wth + 3 * WSZ, wtl + 3 * WSZ, ob, ob, ob,
        out, nullptr, nullptr, nullptr, nullptr, nullptr, nullptr);
}

// round 6
// speedup vs baseline: 2.7781x; 1.0198x over previous
#include <cuda_runtime.h>
#include <cuda_bf16.h>
#include <cstdint>

// Problem constants
#define BATCH   4
#define SEQ     2048
#define DEMB    1024
#define NHEADS  16
#define HDIM    64
#define MROWS   (BATCH * SEQ)   // 8192

// scale folded into Q projection: 1/sqrt(64) * log2(e)
#define QSCALE 0.18033688011112042f

// ---------------- scratch (device globals) -----------------------------------
__device__ __nv_bfloat16 g_xhi[(size_t)MROWS * DEMB];
__device__ __nv_bfloat16 g_xlo[(size_t)MROWS * DEMB];
__device__ __nv_bfloat16 g_qh[(size_t)MROWS * DEMB];
__device__ __nv_bfloat16 g_ql[(size_t)MROWS * DEMB];
__device__ __nv_bfloat16 g_kh[(size_t)MROWS * DEMB];
__device__ __nv_bfloat16 g_kl[(size_t)MROWS * DEMB];
__device__ __nv_bfloat16 g_vh[(size_t)MROWS * DEMB];
__device__ __nv_bfloat16 g_vl[(size_t)MROWS * DEMB];
__device__ __nv_bfloat16 g_wthi[(size_t)4 * DEMB * DEMB];
__device__ __nv_bfloat16 g_wtlo[(size_t)4 * DEMB * DEMB];

// ---------------- helpers -----------------------------------------------------
__device__ __forceinline__ uint32_t s2u(const void* p) {
    uint32_t a;
    asm("{ .reg .u64 t; cvta.to.shared.u64 t, %1; cvt.u32.u64 %0, t; }"
        : "=r"(a) : "l"(p));
    return a;
}
__device__ __forceinline__ void cp16(uint32_t dst, const void* src) {
    asm volatile("cp.async.cg.shared.global [%0], [%1], 16;"
                 :: "r"(dst), "l"(src));
}
__device__ __forceinline__ void cp_commit() {
    asm volatile("cp.async.commit_group;");
}
template <int N>
__device__ __forceinline__ void cp_wait() {
    asm volatile("cp.async.wait_group %0;" :: "n"(N));
}
__device__ __forceinline__ void ldsm_x4(uint32_t* r, uint32_t addr) {
    asm volatile("ldmatrix.sync.aligned.m8n8.x4.shared.b16 {%0,%1,%2,%3}, [%4];"
                 : "=r"(r[0]), "=r"(r[1]), "=r"(r[2]), "=r"(r[3]) : "r"(addr));
}
__device__ __forceinline__ void ldsm_x4t(uint32_t* r, uint32_t addr) {
    asm volatile("ldmatrix.sync.aligned.m8n8.x4.trans.shared.b16 {%0,%1,%2,%3}, [%4];"
                 : "=r"(r[0]), "=r"(r[1]), "=r"(r[2]), "=r"(r[3]) : "r"(addr));
}
__device__ __forceinline__ void mma16816(float* c, const uint32_t* a,
                                         const uint32_t* b) {
    asm volatile(
        "mma.sync.aligned.m16n8k16.row.col.f32.bf16.bf16.f32 "
        "{%0,%1,%2,%3}, {%4,%5,%6,%7}, {%8,%9}, {%0,%1,%2,%3};"
        : "+f"(c[0]), "+f"(c[1]), "+f"(c[2]), "+f"(c[3])
        : "r"(a[0]), "r"(a[1]), "r"(a[2]), "r"(a[3]), "r"(b[0]), "r"(b[1]));
}
__device__ __forceinline__ uint32_t pack_bf2(float lo, float hi) {
    uint32_t r;
    asm("cvt.rn.bf16x2.f32 %0, %1, %2;" : "=r"(r) : "f"(hi), "f"(lo));
    return r;
}
__device__ __forceinline__ float ex2f(float x) {
    float r;
    asm("ex2.approx.f32 %0, %1;" : "=f"(r) : "f"(x));
    return r;
}

// ---------------- fp32 -> bf16 hi/lo split (elementwise) --------------------
__global__ void __launch_bounds__(256) convert_split_kernel(
    const float* __restrict__ in, __nv_bfloat16* __restrict__ hi,
    __nv_bfloat16* __restrict__ lo)
{
    size_t i = (size_t)blockIdx.x * blockDim.x + threadIdx.x;
    float4 v = ((const float4*)in)[i];
    float vv[4] = {v.x, v.y, v.z, v.w};
    ushort4 h, l;
    unsigned short* hp = &h.x;
    unsigned short* lp = &l.x;
#pragma unroll
    for (int j = 0; j < 4; j++) {
        __nv_bfloat16 hb = __float2bfloat16_rn(vv[j]);
        float res = vv[j] - __bfloat162float(hb);
        __nv_bfloat16 lb = __float2bfloat16_rn(res);
        hp[j] = __bfloat16_as_ushort(hb);
        lp[j] = __bfloat16_as_ushort(lb);
    }
    ((ushort4*)hi)[i] = h;
    ((ushort4*)lo)[i] = l;
}

// ---------------- all 4 weights: W[K,N] -> W^T[N,K] bf16 hi/lo ---------------
__global__ void __launch_bounds__(256) wconvert4_kernel(
    const float* __restrict__ W0, const float* __restrict__ W1,
    const float* __restrict__ W2, const float* __restrict__ W3,
    __nv_bfloat16* __restrict__ Thi, __nv_bfloat16* __restrict__ Tlo)
{
    __shared__ float t[32][33];
    const float* W = blockIdx.z == 0 ? W0 : (blockIdx.z == 1 ? W1 :
                     (blockIdx.z == 2 ? W2 : W3));
    size_t base = (size_t)blockIdx.z * DEMB * DEMB;
    int n0 = blockIdx.x * 32;
    int k0 = blockIdx.y * 32;
    int x = threadIdx.x;
    int y = threadIdx.y;
#pragma unroll
    for (int r = y; r < 32; r += 8)
        t[r][x] = W[(size_t)(k0 + r) * DEMB + n0 + x];
    __syncthreads();
#pragma unroll
    for (int r = y; r < 32; r += 8) {
        float v = t[x][r];
        __nv_bfloat16 hb = __float2bfloat16_rn(v);
        float res = v - __bfloat162float(hb);
        __nv_bfloat16 lb = __float2bfloat16_rn(res);
        size_t o = base + (size_t)(n0 + r) * DEMB + k0 + x;
        Thi[o] = hb;
        Tlo[o] = lb;
    }
}

// ---------------- HMMA GEMM v3: 256x128 tile, 512 thr, 3-stage ---------------
#define GBK   32
#define GASTR 40                               // smem row stride (bf16)
#define ATILE (256 * GASTR * 2)                // 20480 B
#define BTILE (128 * GASTR * 2)                // 10240 B
#define STAGEB (2 * ATILE + 2 * BTILE)         // 61440
#define GSMEM (3 * STAGEB)                     // 184320

__global__ void __launch_bounds__(512, 1) gemm256_kernel(
    const __nv_bfloat16* __restrict__ Ahi, const __nv_bfloat16* __restrict__ Alo,
    const __nv_bfloat16* __restrict__ Wh,  const __nv_bfloat16* __restrict__ Wl,
    const float* __restrict__ b0, const float* __restrict__ b1,
    const float* __restrict__ b2,
    float* __restrict__ Cf,
    __nv_bfloat16* __restrict__ h0, __nv_bfloat16* __restrict__ l0,
    __nv_bfloat16* __restrict__ h1, __nv_bfloat16* __restrict__ l1,
    __nv_bfloat16* __restrict__ h2, __nv_bfloat16* __restrict__ l2)
{
    extern __shared__ __align__(128) char smg[];
    const int tid  = threadIdx.x;
    const int wid  = tid >> 5;
    const int lane = tid & 31;
    const int bnx = blockIdx.x;
    const int bm  = blockIdx.y;
    const int wsel = bnx >> 3;
    const int bn   = bnx & 7;
    const int wm = wid & 3;                  // 4 m positions x 64 rows
    const int wn = wid >> 2;                 // 4 n positions x 32 cols
    const uint32_t sb = s2u(smg);

    const size_t WSZ = (size_t)DEMB * DEMB;
    const __nv_bfloat16* Asrc[2] = {
        Ahi + (size_t)bm * 256 * DEMB, Alo + (size_t)bm * 256 * DEMB };
    const __nv_bfloat16* Bsrc[2] = {
        Wh + wsel * WSZ + (size_t)bn * 128 * DEMB,
        Wl + wsel * WSZ + (size_t)bn * 128 * DEMB };
    const float* bias = wsel == 0 ? b0 : (wsel == 1 ? b1 : b2);
    __nv_bfloat16* Ch = wsel == 0 ? h0 : (wsel == 1 ? h1 : h2);
    __nv_bfloat16* Cl = wsel == 0 ? l0 : (wsel == 1 ? l1 : l2);
    const float scl = (Cf == nullptr && wsel == 0) ? QSCALE : 1.0f;

    // 3072 16B chunks per stage, 6 per thread
    auto load_tile = [&](int stage, int k0) {
        uint32_t st = sb + stage * STAGEB;
#pragma unroll
        for (int i = 0; i < 6; i++) {
            int f = i * 512 + tid;
            if (f < 2048) {                        // A arrays
                int arr = f >> 10, rem = f & 1023;
                int row = rem >> 2, kc = rem & 3;
                cp16(st + arr * ATILE + (row * GASTR + kc * 8) * 2,
                     Asrc[arr] + (size_t)row * DEMB + k0 + kc * 8);
            } else {                               // B arrays
                int fb = f - 2048;
                int arr = fb >> 9, rem = fb & 511;
                int row = rem >> 2, kc = rem & 3;
                cp16(st + 2 * ATILE + arr * BTILE + (row * GASTR + kc * 8) * 2,
                     Bsrc[arr] + (size_t)row * DEMB + k0 + kc * 8);
            }
        }
    };

    float acc[4][4][4];
#pragma unroll
    for (int mt = 0; mt < 4; mt++)
#pragma unroll
        for (int nt = 0; nt < 4; nt++)
#pragma unroll
            for (int e = 0; e < 4; e++) acc[mt][nt][e] = 0.0f;

    const int lr = lane & 7, sec = lane >> 3;
    const int a_row = (sec & 1) * 8 + lr;
    const int a_kof = (sec >> 1) * 8;
    const int b_row = (sec >> 1) * 8 + lr;
    const int b_kof = (sec & 1) * 8;

    load_tile(0, 0);
    cp_commit();
    load_tile(1, GBK);
    cp_commit();

    const int NIT = DEMB / GBK;   // 32
    for (int i = 0; i < NIT; i++) {
        cp_wait<1>();
        __syncthreads();
        if (i + 2 < NIT) load_tile((i + 2) % 3, (i + 2) * GBK);
        cp_commit();

        uint32_t st  = sb + (i % 3) * STAGEB;
        uint32_t sAh = st, sAl = st + ATILE;
        uint32_t sBh = st + 2 * ATILE, sBl = sBh + BTILE;

#pragma unroll
        for (int ks = 0; ks < 2; ks++) {
            uint32_t ah[4][4], al[4][4];
#pragma unroll
            for (int mt = 0; mt < 4; mt++) {
                uint32_t off = ((wm * 64 + mt * 16 + a_row) * GASTR
                                + ks * 16 + a_kof) * 2;
                ldsm_x4(ah[mt], sAh + off);
                ldsm_x4(al[mt], sAl + off);
            }
#pragma unroll
            for (int p = 0; p < 2; p++) {     // n-tiles 2p, 2p+1
                uint32_t off = ((wn * 32 + p * 16 + b_row) * GASTR
                                + ks * 16 + b_kof) * 2;
                uint32_t bh[4], bl[4];
                ldsm_x4(bh, sBh + off);
                ldsm_x4(bl, sBl + off);
#pragma unroll
                for (int mt = 0; mt < 4; mt++) {
                    mma16816(acc[mt][2 * p],     ah[mt], &bh[0]);
                    mma16816(acc[mt][2 * p],     ah[mt], &bl[0]);
                    mma16816(acc[mt][2 * p],     al[mt], &bh[0]);
                    mma16816(acc[mt][2 * p + 1], ah[mt], &bh[2]);
                    mma16816(acc[mt][2 * p + 1], ah[mt], &bl[2]);
                    mma16816(acc[mt][2 * p + 1], al[mt], &bh[2]);
                }
            }
        }
        __syncthreads();
    }

    // epilogue
    const int g  = lane >> 2;
    const int cc = (lane & 3) * 2;
#pragma unroll
    for (int mt = 0; mt < 4; mt++) {
        int row0 = bm * 256 + wm * 64 + mt * 16 + g;
#pragma unroll
        for (int nt = 0; nt < 4; nt++) {
            int col = bn * 128 + wn * 32 + nt * 8 + cc;
            float2 b2v = *(const float2*)(bias + col);
            float v0 = (acc[mt][nt][0] + b2v.x) * scl;
            float v1 = (acc[mt][nt][1] + b2v.y) * scl;
            float v2 = (acc[mt][nt][2] + b2v.x) * scl;
            float v3 = (acc[mt][nt][3] + b2v.y) * scl;
            if (Cf) {
                *(float2*)(Cf + (size_t)row0 * DEMB + col) = make_float2(v0, v1);
                *(float2*)(Cf + (size_t)(row0 + 8) * DEMB + col) = make_float2(v2, v3);
            } else {
                uint32_t hh0 = pack_bf2(v0, v1);
                uint32_t hh1 = pack_bf2(v2, v3);
                float r0 = v0 - __uint_as_float(hh0 << 16);
                float r1 = v1 - __uint_as_float(hh0 & 0xFFFF0000u);
                float r2 = v2 - __uint_as_float(hh1 << 16);
                float r3 = v3 - __uint_as_float(hh1 & 0xFFFF0000u);
                *(uint32_t*)(Ch + (size_t)row0 * DEMB + col) = hh0;
                *(uint32_t*)(Ch + (size_t)(row0 + 8) * DEMB + col) = hh1;
                *(uint32_t*)(Cl + (size_t)row0 * DEMB + col) = pack_bf2(r0, r1);
                *(uint32_t*)(Cl + (size_t)(row0 + 8) * DEMB + col) = pack_bf2(r2, r3);
            }
        }
    }
}

// ---------------- HMMA flash attention: 3-stage KV, log2-domain softmax ------
#define AQ   256
#define AKV  64
#define QSTR 72
#define QBYTES (AQ * QSTR * 2)        // 36864 per array
#define KVT (AKV * QSTR * 2)          // 9216 per array
#define KVSTG (4 * KVT)               // 36864 per stage
#define ASMEM (2 * QBYTES + 3 * KVSTG)  // 184320

__global__ void __launch_bounds__(256, 1) attn_mma_kernel(
    const __nv_bfloat16* __restrict__ Qh, const __nv_bfloat16* __restrict__ Ql,
    const __nv_bfloat16* __restrict__ Kh, const __nv_bfloat16* __restrict__ Kl,
    const __nv_bfloat16* __restrict__ Vh, const __nv_bfloat16* __restrict__ Vl,
    __nv_bfloat16* __restrict__ Oh, __nv_bfloat16* __restrict__ Ol)
{
    extern __shared__ __align__(128) char sma[];
    const int tid  = threadIdx.x;
    const int wid  = tid >> 5;
    const int lane = tid & 31;
    const int qb = blockIdx.x, h = blockIdx.y, b = blockIdx.z;

    const uint32_t sb  = s2u(sma);
    const uint32_t sQ0 = sb, sQ1 = sb + QBYTES;
    const uint32_t kvb = sb + 2 * QBYTES;

    const size_t hoff = (size_t)h * HDIM;
    const size_t qrow0 = (size_t)(b * SEQ + qb * AQ);
    const __nv_bfloat16* kvsrc[4] = {
        Kh + (size_t)(b * SEQ) * DEMB + hoff, Kl + (size_t)(b * SEQ) * DEMB + hoff,
        Vh + (size_t)(b * SEQ) * DEMB + hoff, Vl + (size_t)(b * SEQ) * DEMB + hoff };

#pragma unroll
    for (int i = 0; i < 16; i++) {
        int f = tid + i * 256;
        int arr = f >> 11;
        int row = (f >> 3) & 255;
        int col = f & 7;
        const __nv_bfloat16* src =
            (arr ? Ql : Qh) + (qrow0 + row) * DEMB + hoff + col * 8;
        cp16((arr ? sQ1 : sQ0) + (row * QSTR + col * 8) * 2, src);
    }
    auto load_kv = [&](int stage, int kb) {
#pragma unroll
        for (int i = 0; i < 8; i++) {
            int f = tid + i * 256;
            int arr = f >> 9;
            int row = (f >> 3) & 63;
            int col = f & 7;
            cp16(kvb + stage * KVSTG + arr * KVT + (row * QSTR + col * 8) * 2,
                 kvsrc[arr] + (size_t)(kb + row) * DEMB + col * 8);
        }
    };
    load_kv(0, 0);
    cp_commit();
    load_kv(1, AKV);
    cp_commit();

    const int lr = lane & 7, sec = lane >> 3;
    const int a_row = (sec & 1) * 8 + lr;
    const int a_kof = (sec >> 1) * 8;
    const int b_row = (sec >> 1) * 8 + lr;
    const int b_kof = (sec & 1) * 8;
    const int v_row = (sec & 1) * 8 + lr;
    const int v_col = (sec >> 1) * 8;
    const int g = lane >> 2;

    float O[2][8][4];
    float m_r[2][2], l_r[2][2];
#pragma unroll
    for (int mt = 0; mt < 2; mt++) {
#pragma unroll
        for (int nt = 0; nt < 8; nt++)
#pragma unroll
            for (int e = 0; e < 4; e++) O[mt][nt][e] = 0.0f;
        m_r[mt][0] = m_r[mt][1] = -1e30f;
        l_r[mt][0] = l_r[mt][1] = 0.0f;
    }

    const int NB = SEQ / AKV;   // 32
    for (int i = 0; i < NB; i++) {
        cp_wait<1>();
        __syncthreads();
        if (i + 2 < NB) load_kv((i + 2) % 3, (i + 2) * AKV);
        cp_commit();

        uint32_t skh = kvb + (i % 3) * KVSTG;
        uint32_t skl = skh + KVT;
        uint32_t svh = skl + KVT;
        uint32_t svl = svh + KVT;

        // ---- S = Q K^T (log2-domain: Q pre-scaled by 0.125*log2e)
        float S[2][8][4];
#pragma unroll
        for (int mt = 0; mt < 2; mt++)
#pragma unroll
            for (int nt = 0; nt < 8; nt++)
#pragma unroll
                for (int e = 0; e < 4; e++) S[mt][nt][e] = 0.0f;

#pragma unroll
        for (int ks = 0; ks < 4; ks++) {
            uint32_t ah[2][4], al[2][4];
#pragma unroll
            for (int mt = 0; mt < 2; mt++) {
                uint32_t off = ((wid * 32 + mt * 16 + a_row) * QSTR + ks * 16 + a_kof) * 2;
                ldsm_x4(ah[mt], sQ0 + off);
                ldsm_x4(al[mt], sQ1 + off);
            }
#pragma unroll
            for (int ng = 0; ng < 4; ng++) {
                uint32_t bh[4], bl[4];
                uint32_t off = ((ng * 16 + b_row) * QSTR + ks * 16 + b_kof) * 2;
                ldsm_x4(bh, skh + off);
                ldsm_x4(bl, skl + off);
#pragma unroll
                for (int mt = 0; mt < 2; mt++) {
                    mma16816(S[mt][2 * ng],     ah[mt], &bh[0]);
                    mma16816(S[mt][2 * ng],     ah[mt], &bl[0]);
                    mma16816(S[mt][2 * ng],     al[mt], &bh[0]);
                    mma16816(S[mt][2 * ng + 1], ah[mt], &bh[2]);
                    mma16816(S[mt][2 * ng + 1], ah[mt], &bl[2]);
                    mma16816(S[mt][2 * ng + 1], al[mt], &bh[2]);
                }
            }
        }

        // ---- online softmax in log2 domain (exp2)
#pragma unroll
        for (int mt = 0; mt < 2; mt++) {
#pragma unroll
            for (int hr = 0; hr < 2; hr++) {
                const int e0 = hr * 2;
                float mx = -1e30f;
#pragma unroll
                for (int nt = 0; nt < 8; nt++)
                    mx = fmaxf(mx, fmaxf(S[mt][nt][e0], S[mt][nt][e0 + 1]));
                mx = fmaxf(mx, __shfl_xor_sync(0xffffffffu, mx, 1));
                mx = fmaxf(mx, __shfl_xor_sync(0xffffffffu, mx, 2));
                float mnew = fmaxf(m_r[mt][hr], mx);
                float corr = ex2f(m_r[mt][hr] - mnew);
                float sum = 0.0f;
#pragma unroll
                for (int nt = 0; nt < 8; nt++) {
                    float p0 = ex2f(S[mt][nt][e0] - mnew);
                    float p1 = ex2f(S[mt][nt][e0 + 1] - mnew);
                    S[mt][nt][e0] = p0; S[mt][nt][e0 + 1] = p1;
                    sum += p0 + p1;
                }
                sum += __shfl_xor_sync(0xffffffffu, sum, 1);
                sum += __shfl_xor_sync(0xffffffffu, sum, 2);
                l_r[mt][hr] = l_r[mt][hr] * corr + sum;
                m_r[mt][hr] = mnew;
#pragma unroll
                for (int nt = 0; nt < 8; nt++) {
                    O[mt][nt][e0]     *= corr;
                    O[mt][nt][e0 + 1] *= corr;
                }
            }
        }

        // ---- O += P V
#pragma unroll
        for (int ks = 0; ks < 4; ks++) {
            uint32_t ph[2][4], pl[2][4];
#pragma unroll
            for (int mt = 0; mt < 2; mt++) {
#pragma unroll
                for (int j = 0; j < 2; j++) {
                    const float* sp = S[mt][2 * ks + j];
                    uint32_t h01 = pack_bf2(sp[0], sp[1]);
                    uint32_t h23 = pack_bf2(sp[2], sp[3]);
                    ph[mt][2 * j]     = h01;
                    ph[mt][2 * j + 1] = h23;
                    float r0 = sp[0] - __uint_as_float(h01 << 16);
                    float r1 = sp[1] - __uint_as_float(h01 & 0xFFFF0000u);
                    float r2 = sp[2] - __uint_as_float(h23 << 16);
                    float r3 = sp[3] - __uint_as_float(h23 & 0xFFFF0000u);
                    pl[mt][2 * j]     = pack_bf2(r0, r1);
                    pl[mt][2 * j + 1] = pack_bf2(r2, r3);
                }
            }
#pragma unroll
            for (int dg = 0; dg < 4; dg++) {
                uint32_t vh[4], vl[4];
                uint32_t off = ((ks * 16 + v_row) * QSTR + dg * 16 + v_col) * 2;
                ldsm_x4t(vh, svh + off);
                ldsm_x4t(vl, svl + off);
#pragma unroll
                for (int mt = 0; mt < 2; mt++) {
                    mma16816(O[mt][2 * dg],     ph[mt], &vh[0]);
                    mma16816(O[mt][2 * dg],     ph[mt], &vl[0]);
                    mma16816(O[mt][2 * dg],     pl[mt], &vh[0]);
                    mma16816(O[mt][2 * dg + 1], ph[mt], &vh[2]);
                    mma16816(O[mt][2 * dg + 1], ph[mt], &vl[2]);
                    mma16816(O[mt][2 * dg + 1], pl[mt], &vh[2]);
                }
            }
        }
    }

    const int t2 = (lane & 3) * 2;
#pragma unroll
    for (int mt = 0; mt < 2; mt++) {
#pragma unroll
        for (int hr = 0; hr < 2; hr++) {
            float inv = 1.0f / l_r[mt][hr];
            size_t row = qrow0 + wid * 32 + mt * 16 + g + hr * 8;
#pragma unroll
            for (int nt = 0; nt < 8; nt++) {
                float o0 = O[mt][nt][2 * hr]     * inv;
                float o1 = O[mt][nt][2 * hr + 1] * inv;
                uint32_t hb = pack_bf2(o0, o1);
                float r0 = o0 - __uint_as_float(hb << 16);
                float r1 = o1 - __uint_as_float(hb & 0xFFFF0000u);
                size_t off = row * DEMB + hoff + nt * 8 + t2;
                *(uint32_t*)(Oh + off) = hb;
                *(uint32_t*)(Ol + off) = pack_bf2(r0, r1);
            }
        }
    }
}

// ---------------- launch -----------------------------------------------------
extern "C" void kernel_launch(void* const* d_in, const int* in_sizes, int n_in,
                              void* d_out, int out_size)
{
    const float* x  = (const float*)d_in[0];
    const float* qw = (const float*)d_in[1];
    const float* qb = (const float*)d_in[2];
    const float* kw = (const float*)d_in[3];
    const float* kb = (const float*)d_in[4];
    const float* vw = (const float*)d_in[5];
    const float* vb = (const float*)d_in[6];
    const float* ow = (const float*)d_in[7];
    const float* ob = (const float*)d_in[8];
    float* out = (float*)d_out;

    __nv_bfloat16 *xh, *xl, *wth, *wtl, *qh, *ql, *kh, *kl, *vh, *vl;
    cudaGetSymbolAddress((void**)&xh, g_xhi);
    cudaGetSymbolAddress((void**)&xl, g_xlo);
    cudaGetSymbolAddress((void**)&wth, g_wthi);
    cudaGetSymbolAddress((void**)&wtl, g_wtlo);
    cudaGetSymbolAddress((void**)&qh, g_qh);
    cudaGetSymbolAddress((void**)&ql, g_ql);
    cudaGetSymbolAddress((void**)&kh, g_kh);
    cudaGetSymbolAddress((void**)&kl, g_kl);
    cudaGetSymbolAddress((void**)&vh, g_vh);
    cudaGetSymbolAddress((void**)&vl, g_vl);

    cudaFuncSetAttribute(gemm256_kernel, cudaFuncAttributeMaxDynamicSharedMemorySize,
                         GSMEM);
    cudaFuncSetAttribute(attn_mma_kernel, cudaFuncAttributeMaxDynamicSharedMemorySize,
                         ASMEM);

    const size_t WSZ = (size_t)DEMB * DEMB;

    convert_split_kernel<<<MROWS * DEMB / 4 / 256, 256>>>(x, xh, xl);
    dim3 wgrid(32, 32, 4), wblk(32, 8);
    wconvert4_kernel<<<wgrid, wblk>>>(qw, kw, vw, ow, wth, wtl);

    // fused QKV projection (Q output pre-scaled by 0.125*log2e)
    dim3 qkv_grid(24, MROWS / 256);
    gemm256_kernel<<<qkv_grid, 512, GSMEM>>>(
        xh, xl, wth, wtl, qb, kb, vb,
        nullptr, qh, ql, kh, kl, vh, vl);

    dim3 attn_grid(SEQ / AQ, NHEADS, BATCH);
    attn_mma_kernel<<<attn_grid, 256, ASMEM>>>(qh, ql, kh, kl, vh, vl, xh, xl);

    // output projection: fp32 out
    dim3 o_grid(8, MROWS / 256);
    gemm256_kernel<<<o_grid, 512, GSMEM>>>(
        xh, xl, wth + 3 * WSZ, wtl + 3 * WSZ, ob, ob, ob,
        out, nullptr, nullptr, nullptr, nullptr, nullptr, nullptr);
}

// round 7
// speedup vs baseline: 2.9458x; 1.0603x over previous
#include <cuda_runtime.h>
#include <cuda_bf16.h>
#include <cstdint>

// Problem constants
#define BATCH   4
#define SEQ     2048
#define DEMB    1024
#define NHEADS  16
#define HDIM    64
#define MROWS   (BATCH * SEQ)   // 8192

// scale folded into Q projection: 1/sqrt(64) * log2(e)
#define QSCALE 0.18033688011112042f

// ---------------- scratch (device globals) -----------------------------------
__device__ __nv_bfloat16 g_xhi[(size_t)MROWS * DEMB];
__device__ __nv_bfloat16 g_xlo[(size_t)MROWS * DEMB];
__device__ __nv_bfloat16 g_qh[(size_t)MROWS * DEMB];
__device__ __nv_bfloat16 g_ql[(size_t)MROWS * DEMB];
__device__ __nv_bfloat16 g_kh[(size_t)MROWS * DEMB];
__device__ __nv_bfloat16 g_kl[(size_t)MROWS * DEMB];
__device__ __nv_bfloat16 g_vh[(size_t)MROWS * DEMB];
__device__ __nv_bfloat16 g_vl[(size_t)MROWS * DEMB];
__device__ __nv_bfloat16 g_wthi[(size_t)4 * DEMB * DEMB];
__device__ __nv_bfloat16 g_wtlo[(size_t)4 * DEMB * DEMB];

// ---------------- helpers -----------------------------------------------------
__device__ __forceinline__ uint32_t s2u(const void* p) {
    uint32_t a;
    asm("{ .reg .u64 t; cvta.to.shared.u64 t, %1; cvt.u32.u64 %0, t; }"
        : "=r"(a) : "l"(p));
    return a;
}
__device__ __forceinline__ void cp16(uint32_t dst, const void* src) {
    asm volatile("cp.async.cg.shared.global [%0], [%1], 16;"
                 :: "r"(dst), "l"(src));
}
__device__ __forceinline__ void cp_commit() {
    asm volatile("cp.async.commit_group;");
}
template <int N>
__device__ __forceinline__ void cp_wait() {
    asm volatile("cp.async.wait_group %0;" :: "n"(N));
}
__device__ __forceinline__ void ldsm_x4(uint32_t* r, uint32_t addr) {
    asm volatile("ldmatrix.sync.aligned.m8n8.x4.shared.b16 {%0,%1,%2,%3}, [%4];"
                 : "=r"(r[0]), "=r"(r[1]), "=r"(r[2]), "=r"(r[3]) : "r"(addr));
}
__device__ __forceinline__ void ldsm_x4t(uint32_t* r, uint32_t addr) {
    asm volatile("ldmatrix.sync.aligned.m8n8.x4.trans.shared.b16 {%0,%1,%2,%3}, [%4];"
                 : "=r"(r[0]), "=r"(r[1]), "=r"(r[2]), "=r"(r[3]) : "r"(addr));
}
__device__ __forceinline__ void mma16816(float* c, const uint32_t* a,
                                         const uint32_t* b) {
    asm volatile(
        "mma.sync.aligned.m16n8k16.row.col.f32.bf16.bf16.f32 "
        "{%0,%1,%2,%3}, {%4,%5,%6,%7}, {%8,%9}, {%0,%1,%2,%3};"
        : "+f"(c[0]), "+f"(c[1]), "+f"(c[2]), "+f"(c[3])
        : "r"(a[0]), "r"(a[1]), "r"(a[2]), "r"(a[3]), "r"(b[0]), "r"(b[1]));
}
__device__ __forceinline__ uint32_t pack_bf2(float lo, float hi) {
    uint32_t r;
    asm("cvt.rn.bf16x2.f32 %0, %1, %2;" : "=r"(r) : "f"(hi), "f"(lo));
    return r;
}
__device__ __forceinline__ float ex2f(float x) {
    float r;
    asm("ex2.approx.f32 %0, %1;" : "=f"(r) : "f"(x));
    return r;
}

// ---------------- fp32 -> bf16 hi/lo split (elementwise) --------------------
__global__ void __launch_bounds__(256) convert_split_kernel(
    const float* __restrict__ in, __nv_bfloat16* __restrict__ hi,
    __nv_bfloat16* __restrict__ lo)
{
    size_t i = (size_t)blockIdx.x * blockDim.x + threadIdx.x;
    float4 v = ((const float4*)in)[i];
    float vv[4] = {v.x, v.y, v.z, v.w};
    ushort4 h, l;
    unsigned short* hp = &h.x;
    unsigned short* lp = &l.x;
#pragma unroll
    for (int j = 0; j < 4; j++) {
        __nv_bfloat16 hb = __float2bfloat16_rn(vv[j]);
        float res = vv[j] - __bfloat162float(hb);
        __nv_bfloat16 lb = __float2bfloat16_rn(res);
        hp[j] = __bfloat16_as_ushort(hb);
        lp[j] = __bfloat16_as_ushort(lb);
    }
    ((ushort4*)hi)[i] = h;
    ((ushort4*)lo)[i] = l;
}

// ---------------- all 4 weights: W[K,N] -> W^T[N,K] bf16 hi/lo ---------------
__global__ void __launch_bounds__(256) wconvert4_kernel(
    const float* __restrict__ W0, const float* __restrict__ W1,
    const float* __restrict__ W2, const float* __restrict__ W3,
    __nv_bfloat16* __restrict__ Thi, __nv_bfloat16* __restrict__ Tlo)
{
    __shared__ float t[32][33];
    const float* W = blockIdx.z == 0 ? W0 : (blockIdx.z == 1 ? W1 :
                     (blockIdx.z == 2 ? W2 : W3));
    size_t base = (size_t)blockIdx.z * DEMB * DEMB;
    int n0 = blockIdx.x * 32;
    int k0 = blockIdx.y * 32;
    int x = threadIdx.x;
    int y = threadIdx.y;
#pragma unroll
    for (int r = y; r < 32; r += 8)
        t[r][x] = W[(size_t)(k0 + r) * DEMB + n0 + x];
    __syncthreads();
#pragma unroll
    for (int r = y; r < 32; r += 8) {
        float v = t[x][r];
        __nv_bfloat16 hb = __float2bfloat16_rn(v);
        float res = v - __bfloat162float(hb);
        __nv_bfloat16 lb = __float2bfloat16_rn(res);
        size_t o = base + (size_t)(n0 + r) * DEMB + k0 + x;
        Thi[o] = hb;
        Tlo[o] = lb;
    }
}

// ---------------- HMMA GEMM: 256x128 tile, 512 thr, 3-stage, 1 barrier/iter --
#define GBK   32
#define GASTR 40
#define ATILE (256 * GASTR * 2)                // 20480 B
#define BTILE (128 * GASTR * 2)                // 10240 B
#define STAGEB (2 * ATILE + 2 * BTILE)         // 61440
#define GSMEM (3 * STAGEB)                     // 184320

__global__ void __launch_bounds__(512, 1) gemm256_kernel(
    const __nv_bfloat16* __restrict__ Ahi, const __nv_bfloat16* __restrict__ Alo,
    const __nv_bfloat16* __restrict__ Wh,  const __nv_bfloat16* __restrict__ Wl,
    const float* __restrict__ b0, const float* __restrict__ b1,
    const float* __restrict__ b2,
    float* __restrict__ Cf,
    __nv_bfloat16* __restrict__ h0, __nv_bfloat16* __restrict__ l0,
    __nv_bfloat16* __restrict__ h1, __nv_bfloat16* __restrict__ l1,
    __nv_bfloat16* __restrict__ h2, __nv_bfloat16* __restrict__ l2)
{
    extern __shared__ __align__(128) char smg[];
    const int tid  = threadIdx.x;
    const int wid  = tid >> 5;
    const int lane = tid & 31;
    const int bnx = blockIdx.x;
    const int bm  = blockIdx.y;
    const int wsel = bnx >> 3;
    const int bn   = bnx & 7;
    const int wm = wid & 3;
    const int wn = wid >> 2;
    const uint32_t sb = s2u(smg);

    const size_t WSZ = (size_t)DEMB * DEMB;
    const __nv_bfloat16* Asrc[2] = {
        Ahi + (size_t)bm * 256 * DEMB, Alo + (size_t)bm * 256 * DEMB };
    const __nv_bfloat16* Bsrc[2] = {
        Wh + wsel * WSZ + (size_t)bn * 128 * DEMB,
        Wl + wsel * WSZ + (size_t)bn * 128 * DEMB };
    const float* bias = wsel == 0 ? b0 : (wsel == 1 ? b1 : b2);
    __nv_bfloat16* Ch = wsel == 0 ? h0 : (wsel == 1 ? h1 : h2);
    __nv_bfloat16* Cl = wsel == 0 ? l0 : (wsel == 1 ? l1 : l2);
    const float scl = (Cf == nullptr && wsel == 0) ? QSCALE : 1.0f;

    auto load_tile = [&](int stage, int k0) {
        uint32_t st = sb + stage * STAGEB;
#pragma unroll
        for (int i = 0; i < 6; i++) {
            int f = i * 512 + tid;
            if (f < 2048) {
                int arr = f >> 10, rem = f & 1023;
                int row = rem >> 2, kc = rem & 3;
                cp16(st + arr * ATILE + (row * GASTR + kc * 8) * 2,
                     Asrc[arr] + (size_t)row * DEMB + k0 + kc * 8);
            } else {
                int fb = f - 2048;
                int arr = fb >> 9, rem = fb & 511;
                int row = rem >> 2, kc = rem & 3;
                cp16(st + 2 * ATILE + arr * BTILE + (row * GASTR + kc * 8) * 2,
                     Bsrc[arr] + (size_t)row * DEMB + k0 + kc * 8);
            }
        }
    };

    float acc[4][4][4];
#pragma unroll
    for (int mt = 0; mt < 4; mt++)
#pragma unroll
        for (int nt = 0; nt < 4; nt++)
#pragma unroll
            for (int e = 0; e < 4; e++) acc[mt][nt][e] = 0.0f;

    const int lr = lane & 7, sec = lane >> 3;
    const int a_row = (sec & 1) * 8 + lr;
    const int a_kof = (sec >> 1) * 8;
    const int b_row = (sec >> 1) * 8 + lr;
    const int b_kof = (sec & 1) * 8;

    load_tile(0, 0);
    cp_commit();
    load_tile(1, GBK);
    cp_commit();

    const int NIT = DEMB / GBK;   // 32
    for (int i = 0; i < NIT; i++) {
        cp_wait<1>();
        __syncthreads();   // stage i ready; all warps done reading stage (i-1)%3
        if (i + 2 < NIT) load_tile((i + 2) % 3, (i + 2) * GBK);  // targets (i-1)%3
        cp_commit();

        uint32_t st  = sb + (i % 3) * STAGEB;
        uint32_t sAh = st, sAl = st + ATILE;
        uint32_t sBh = st + 2 * ATILE, sBl = sBh + BTILE;

#pragma unroll
        for (int ks = 0; ks < 2; ks++) {
            uint32_t ah[4][4], al[4][4];
#pragma unroll
            for (int mt = 0; mt < 4; mt++) {
                uint32_t off = ((wm * 64 + mt * 16 + a_row) * GASTR
                                + ks * 16 + a_kof) * 2;
                ldsm_x4(ah[mt], sAh + off);
                ldsm_x4(al[mt], sAl + off);
            }
#pragma unroll
            for (int p = 0; p < 2; p++) {
                uint32_t off = ((wn * 32 + p * 16 + b_row) * GASTR
                                + ks * 16 + b_kof) * 2;
                uint32_t bh[4], bl[4];
                ldsm_x4(bh, sBh + off);
                ldsm_x4(bl, sBl + off);
#pragma unroll
                for (int mt = 0; mt < 4; mt++) {
                    mma16816(acc[mt][2 * p],     ah[mt], &bh[0]);
                    mma16816(acc[mt][2 * p],     ah[mt], &bl[0]);
                    mma16816(acc[mt][2 * p],     al[mt], &bh[0]);
                    mma16816(acc[mt][2 * p + 1], ah[mt], &bh[2]);
                    mma16816(acc[mt][2 * p + 1], ah[mt], &bl[2]);
                    mma16816(acc[mt][2 * p + 1], al[mt], &bh[2]);
                }
            }
        }
        // no trailing barrier: next iter's top barrier provides the protection
    }

    const int g  = lane >> 2;
    const int cc = (lane & 3) * 2;
#pragma unroll
    for (int mt = 0; mt < 4; mt++) {
        int row0 = bm * 256 + wm * 64 + mt * 16 + g;
#pragma unroll
        for (int nt = 0; nt < 4; nt++) {
            int col = bn * 128 + wn * 32 + nt * 8 + cc;
            float2 b2v = *(const float2*)(bias + col);
            float v0 = (acc[mt][nt][0] + b2v.x) * scl;
            float v1 = (acc[mt][nt][1] + b2v.y) * scl;
            float v2 = (acc[mt][nt][2] + b2v.x) * scl;
            float v3 = (acc[mt][nt][3] + b2v.y) * scl;
            if (Cf) {
                *(float2*)(Cf + (size_t)row0 * DEMB + col) = make_float2(v0, v1);
                *(float2*)(Cf + (size_t)(row0 + 8) * DEMB + col) = make_float2(v2, v3);
            } else {
                uint32_t hh0 = pack_bf2(v0, v1);
                uint32_t hh1 = pack_bf2(v2, v3);
                float r0 = v0 - __uint_as_float(hh0 << 16);
                float r1 = v1 - __uint_as_float(hh0 & 0xFFFF0000u);
                float r2 = v2 - __uint_as_float(hh1 << 16);
                float r3 = v3 - __uint_as_float(hh1 & 0xFFFF0000u);
                *(uint32_t*)(Ch + (size_t)row0 * DEMB + col) = hh0;
                *(uint32_t*)(Ch + (size_t)(row0 + 8) * DEMB + col) = hh1;
                *(uint32_t*)(Cl + (size_t)row0 * DEMB + col) = pack_bf2(r0, r1);
                *(uint32_t*)(Cl + (size_t)(row0 + 8) * DEMB + col) = pack_bf2(r2, r3);
            }
        }
    }
}

// ---------------- HMMA flash attention: AQ=128, 2 CTAs/SM --------------------
// 8 warps x 16 q rows. 2-stage KV ring, 1 barrier/iter, log2-domain softmax.
#define AQ   128
#define AKV  64
#define QSTR 72
#define QBYTES (AQ * QSTR * 2)          // 18432 per array
#define KVT (AKV * QSTR * 2)            // 9216 per array
#define KVSTG (4 * KVT)                 // 36864 per stage
#define ASMEM (2 * QBYTES + 2 * KVSTG)  // 110592 -> 2 CTAs/SM

__global__ void __launch_bounds__(256, 2) attn_mma_kernel(
    const __nv_bfloat16* __restrict__ Qh, const __nv_bfloat16* __restrict__ Ql,
    const __nv_bfloat16* __restrict__ Kh, const __nv_bfloat16* __restrict__ Kl,
    const __nv_bfloat16* __restrict__ Vh, const __nv_bfloat16* __restrict__ Vl,
    __nv_bfloat16* __restrict__ Oh, __nv_bfloat16* __restrict__ Ol)
{
    extern __shared__ __align__(128) char sma[];
    const int tid  = threadIdx.x;
    const int wid  = tid >> 5;
    const int lane = tid & 31;
    const int qb = blockIdx.x, h = blockIdx.y, b = blockIdx.z;

    const uint32_t sb  = s2u(sma);
    const uint32_t sQ0 = sb, sQ1 = sb + QBYTES;
    const uint32_t kvb = sb + 2 * QBYTES;

    const size_t hoff = (size_t)h * HDIM;
    const size_t qrow0 = (size_t)(b * SEQ + qb * AQ);
    const __nv_bfloat16* kvsrc[4] = {
        Kh + (size_t)(b * SEQ) * DEMB + hoff, Kl + (size_t)(b * SEQ) * DEMB + hoff,
        Vh + (size_t)(b * SEQ) * DEMB + hoff, Vl + (size_t)(b * SEQ) * DEMB + hoff };

    // Q: 128 rows x 8 chunks x 2 arrays = 2048 chunks, 8/thread? -> 1024*2/256 = 8
#pragma unroll
    for (int i = 0; i < 8; i++) {
        int f = tid + i * 256;
        int arr = f >> 10;              // 0: hi, 1: lo
        int row = (f >> 3) & 127;
        int col = f & 7;
        const __nv_bfloat16* src =
            (arr ? Ql : Qh) + (qrow0 + row) * DEMB + hoff + col * 8;
        cp16((arr ? sQ1 : sQ0) + (row * QSTR + col * 8) * 2, src);
    }
    auto load_kv = [&](int stage, int kb) {
#pragma unroll
        for (int i = 0; i < 8; i++) {
            int f = tid + i * 256;
            int arr = f >> 9;
            int row = (f >> 3) & 63;
            int col = f & 7;
            cp16(kvb + stage * KVSTG + arr * KVT + (row * QSTR + col * 8) * 2,
                 kvsrc[arr] + (size_t)(kb + row) * DEMB + col * 8);
        }
    };
    load_kv(0, 0);
    cp_commit();

    const int lr = lane & 7, sec = lane >> 3;
    const int a_row = (sec & 1) * 8 + lr;
    const int a_kof = (sec >> 1) * 8;
    const int b_row = (sec >> 1) * 8 + lr;
    const int b_kof = (sec & 1) * 8;
    const int v_row = (sec & 1) * 8 + lr;
    const int v_col = (sec >> 1) * 8;
    const int g = lane >> 2;

    float O[8][4];
    float m_r[2], l_r[2];
#pragma unroll
    for (int nt = 0; nt < 8; nt++)
#pragma unroll
        for (int e = 0; e < 4; e++) O[nt][e] = 0.0f;
    m_r[0] = m_r[1] = -1e30f;
    l_r[0] = l_r[1] = 0.0f;

    const int NB = SEQ / AKV;   // 32
    for (int i = 0; i < NB; i++) {
        cp_wait<0>();            // stage i%2 ready (single group in flight)
        __syncthreads();         // + all warps done reading stage (i-1)%2
        if (i + 1 < NB) load_kv((i + 1) & 1, (i + 1) * AKV);
        cp_commit();

        uint32_t skh = kvb + (i & 1) * KVSTG;
        uint32_t skl = skh + KVT;
        uint32_t svh = skl + KVT;
        uint32_t svl = svh + KVT;

        // ---- S = Q K^T (log2 domain: Q pre-scaled by 0.125*log2e)
        float S[8][4];
#pragma unroll
        for (int nt = 0; nt < 8; nt++)
#pragma unroll
            for (int e = 0; e < 4; e++) S[nt][e] = 0.0f;

#pragma unroll
        for (int ks = 0; ks < 4; ks++) {
            uint32_t ah[4], al[4];
            uint32_t aoff = ((wid * 16 + a_row) * QSTR + ks * 16 + a_kof) * 2;
            ldsm_x4(ah, sQ0 + aoff);
            ldsm_x4(al, sQ1 + aoff);
#pragma unroll
            for (int ng = 0; ng < 4; ng++) {
                uint32_t bh[4], bl[4];
                uint32_t off = ((ng * 16 + b_row) * QSTR + ks * 16 + b_kof) * 2;
                ldsm_x4(bh, skh + off);
                ldsm_x4(bl, skl + off);
                mma16816(S[2 * ng],     ah, &bh[0]);
                mma16816(S[2 * ng],     ah, &bl[0]);
                mma16816(S[2 * ng],     al, &bh[0]);
                mma16816(S[2 * ng + 1], ah, &bh[2]);
                mma16816(S[2 * ng + 1], ah, &bl[2]);
                mma16816(S[2 * ng + 1], al, &bh[2]);
            }
        }

        // ---- online softmax (exp2)
#pragma unroll
        for (int hr = 0; hr < 2; hr++) {
            const int e0 = hr * 2;
            float mx = -1e30f;
#pragma unroll
            for (int nt = 0; nt < 8; nt++)
                mx = fmaxf(mx, fmaxf(S[nt][e0], S[nt][e0 + 1]));
            mx = fmaxf(mx, __shfl_xor_sync(0xffffffffu, mx, 1));
            mx = fmaxf(mx, __shfl_xor_sync(0xffffffffu, mx, 2));
            float mnew = fmaxf(m_r[hr], mx);
            float corr = ex2f(m_r[hr] - mnew);
            float sum = 0.0f;
#pragma unroll
            for (int nt = 0; nt < 8; nt++) {
                float p0 = ex2f(S[nt][e0] - mnew);
                float p1 = ex2f(S[nt][e0 + 1] - mnew);
                S[nt][e0] = p0; S[nt][e0 + 1] = p1;
                sum += p0 + p1;
            }
            sum += __shfl_xor_sync(0xffffffffu, sum, 1);
            sum += __shfl_xor_sync(0xffffffffu, sum, 2);
            l_r[hr] = l_r[hr] * corr + sum;
            m_r[hr] = mnew;
#pragma unroll
            for (int nt = 0; nt < 8; nt++) {
                O[nt][e0]     *= corr;
                O[nt][e0 + 1] *= corr;
            }
        }

        // ---- O += P V
#pragma unroll
        for (int ks = 0; ks < 4; ks++) {
            uint32_t ph[4], pl[4];
#pragma unroll
            for (int j = 0; j < 2; j++) {
                const float* sp = S[2 * ks + j];
                uint32_t h01 = pack_bf2(sp[0], sp[1]);
                uint32_t h23 = pack_bf2(sp[2], sp[3]);
                ph[2 * j]     = h01;
                ph[2 * j + 1] = h23;
                float r0 = sp[0] - __uint_as_float(h01 << 16);
                float r1 = sp[1] - __uint_as_float(h01 & 0xFFFF0000u);
                float r2 = sp[2] - __uint_as_float(h23 << 16);
                float r3 = sp[3] - __uint_as_float(h23 & 0xFFFF0000u);
                pl[2 * j]     = pack_bf2(r0, r1);
                pl[2 * j + 1] = pack_bf2(r2, r3);
            }
#pragma unroll
            for (int dg = 0; dg < 4; dg++) {
                uint32_t vh[4], vl[4];
                uint32_t off = ((ks * 16 + v_row) * QSTR + dg * 16 + v_col) * 2;
                ldsm_x4t(vh, svh + off);
                ldsm_x4t(vl, svl + off);
                mma16816(O[2 * dg],     ph, &vh[0]);
                mma16816(O[2 * dg],     ph, &vl[0]);
                mma16816(O[2 * dg],     pl, &vh[0]);
                mma16816(O[2 * dg + 1], ph, &vh[2]);
                mma16816(O[2 * dg + 1], ph, &vl[2]);
                mma16816(O[2 * dg + 1], pl, &vh[2]);
            }
        }
    }

    const int t2 = (lane & 3) * 2;
#pragma unroll
    for (int hr = 0; hr < 2; hr++) {
        float inv = 1.0f / l_r[hr];
        size_t row = qrow0 + wid * 16 + g + hr * 8;
#pragma unroll
        for (int nt = 0; nt < 8; nt++) {
            float o0 = O[nt][2 * hr]     * inv;
            float o1 = O[nt][2 * hr + 1] * inv;
            uint32_t hb = pack_bf2(o0, o1);
            float r0 = o0 - __uint_as_float(hb << 16);
            float r1 = o1 - __uint_as_float(hb & 0xFFFF0000u);
            size_t off = row * DEMB + hoff + nt * 8 + t2;
            *(uint32_t*)(Oh + off) = hb;
            *(uint32_t*)(Ol + off) = pack_bf2(r0, r1);
        }
    }
}

// ---------------- launch -----------------------------------------------------
extern "C" void kernel_launch(void* const* d_in, const int* in_sizes, int n_in,
                              void* d_out, int out_size)
{
    const float* x  = (const float*)d_in[0];
    const float* qw = (const float*)d_in[1];
    const float* qb = (const float*)d_in[2];
    const float* kw = (const float*)d_in[3];
    const float* kb = (const float*)d_in[4];
    const float* vw = (const float*)d_in[5];
    const float* vb = (const float*)d_in[6];
    const float* ow = (const float*)d_in[7];
    const float* ob = (const float*)d_in[8];
    float* out = (float*)d_out;

    __nv_bfloat16 *xh, *xl, *wth, *wtl, *qh, *ql, *kh, *kl, *vh, *vl;
    cudaGetSymbolAddress((void**)&xh, g_xhi);
    cudaGetSymbolAddress((void**)&xl, g_xlo);
    cudaGetSymbolAddress((void**)&wth, g_wthi);
    cudaGetSymbolAddress((void**)&wtl, g_wtlo);
    cudaGetSymbolAddress((void**)&qh, g_qh);
    cudaGetSymbolAddress((void**)&ql, g_ql);
    cudaGetSymbolAddress((void**)&kh, g_kh);
    cudaGetSymbolAddress((void**)&kl, g_kl);
    cudaGetSymbolAddress((void**)&vh, g_vh);
    cudaGetSymbolAddress((void**)&vl, g_vl);

    cudaFuncSetAttribute(gemm256_kernel, cudaFuncAttributeMaxDynamicSharedMemorySize,
                         GSMEM);
    cudaFuncSetAttribute(attn_mma_kernel, cudaFuncAttributeMaxDynamicSharedMemorySize,
                         ASMEM);

    const size_t WSZ = (size_t)DEMB * DEMB;

    convert_split_kernel<<<MROWS * DEMB / 4 / 256, 256>>>(x, xh, xl);
    dim3 wgrid(32, 32, 4), wblk(32, 8);
    wconvert4_kernel<<<wgrid, wblk>>>(qw, kw, vw, ow, wth, wtl);

    dim3 qkv_grid(24, MROWS / 256);
    gemm256_kernel<<<qkv_grid, 512, GSMEM>>>(
        xh, xl, wth, wtl, qb, kb, vb,
        nullptr, qh, ql, kh, kl, vh, vl);

    dim3 attn_grid(SEQ / AQ, NHEADS, BATCH);   // (16, 16, 4) = 1024 CTAs
    attn_mma_kernel<<<attn_grid, 256, ASMEM>>>(qh, ql, kh, kl, vh, vl, xh, xl);

    dim3 o_grid(8, MROWS / 256);
    gemm256_kernel<<<o_grid, 512, GSMEM>>>(
        xh, xl, wth + 3 * WSZ, wtl + 3 * WSZ, ob, ob, ob,
        out, nullptr, nullptr, nullptr, nullptr, nullptr, nullptr);
}